// round 6
// baseline (speedup 1.0000x reference)
#include <cuda_runtime.h>
#include <cuda_bf16.h>
#include <cstdint>

// Problem constants (Qwen3MoeSparseMoeBlock_2413771621126)
#define T_TOK   1024
#define HID     2048
#define NEXP    16
#define TOPK    4
#define INTER   768
#define INTER2  1536

// ---------------- device scratch (static; allocation-free) ----------------
__device__ int   g_cnt[NEXP];
__device__ int   g_tok[NEXP * T_TOK];
__device__ float g_wt [NEXP * T_TOK];

__device__ __align__(128) __nv_bfloat16 g_xhi[(size_t)T_TOK * HID];
__device__ __align__(128) __nv_bfloat16 g_xlo[(size_t)T_TOK * HID];
__device__ __align__(128) __nv_bfloat16 g_hhi[(size_t)NEXP * T_TOK * INTER];
__device__ __align__(128) __nv_bfloat16 g_hlo[(size_t)NEXP * T_TOK * INTER];

// ---------------- helpers ----------------
__device__ __forceinline__ uint32_t smem_u32(const void* p) {
    uint32_t a;
    asm("{ .reg .u64 t; cvta.to.shared.u64 t, %1; cvt.u32.u64 %0, t; }" : "=r"(a) : "l"(p));
    return a;
}

__device__ __forceinline__ void split4(float4 f, uint2& hi, uint2& lo) {
    __nv_bfloat16 hx = __float2bfloat16(f.x);
    __nv_bfloat16 hy = __float2bfloat16(f.y);
    __nv_bfloat16 hz = __float2bfloat16(f.z);
    __nv_bfloat16 hw = __float2bfloat16(f.w);
    __nv_bfloat16 lx = __float2bfloat16(f.x - __bfloat162float(hx));
    __nv_bfloat16 ly = __float2bfloat16(f.y - __bfloat162float(hy));
    __nv_bfloat16 lz = __float2bfloat16(f.z - __bfloat162float(hz));
    __nv_bfloat16 lw = __float2bfloat16(f.w - __bfloat162float(hw));
    hi.x = ((uint32_t)__bfloat16_as_ushort(hy) << 16) | __bfloat16_as_ushort(hx);
    hi.y = ((uint32_t)__bfloat16_as_ushort(hw) << 16) | __bfloat16_as_ushort(hz);
    lo.x = ((uint32_t)__bfloat16_as_ushort(ly) << 16) | __bfloat16_as_ushort(lx);
    lo.y = ((uint32_t)__bfloat16_as_ushort(lw) << 16) | __bfloat16_as_ushort(lz);
}
__device__ __forceinline__ void split1(float f, uint16_t& hi, uint16_t& lo) {
    __nv_bfloat16 h = __float2bfloat16(f);
    __nv_bfloat16 l = __float2bfloat16(f - __bfloat162float(h));
    hi = __bfloat16_as_ushort(h);
    lo = __bfloat16_as_ushort(l);
}

#define MMA_BF16(d, a, b) \
    asm volatile("mma.sync.aligned.m16n8k16.row.col.f32.bf16.bf16.f32 " \
        "{%0,%1,%2,%3}, {%4,%5,%6,%7}, {%8,%9}, {%0,%1,%2,%3};" \
        : "+f"((d)[0]), "+f"((d)[1]), "+f"((d)[2]), "+f"((d)[3]) \
        : "r"((a)[0]), "r"((a)[1]), "r"((a)[2]), "r"((a)[3]), \
          "r"((b)[0]), "r"((b)[1]))

#define LDSM4(r, a) \
    asm volatile("ldmatrix.sync.aligned.m8n8.x4.shared.b16 {%0,%1,%2,%3}, [%4];" \
        : "=r"((r)[0]), "=r"((r)[1]), "=r"((r)[2]), "=r"((r)[3]) : "r"(a))
#define LDSM4T(r, a) \
    asm volatile("ldmatrix.sync.aligned.m8n8.x4.trans.shared.b16 {%0,%1,%2,%3}, [%4];" \
        : "=r"((r)[0]), "=r"((r)[1]), "=r"((r)[2]), "=r"((r)[3]) : "r"(a))

#define CP16(dst, src) \
    asm volatile("cp.async.cg.shared.global [%0], [%1], 16;" \
        :: "r"(dst), "l"(__cvta_generic_to_global(src)))
#define CP_COMMIT() asm volatile("cp.async.commit_group;" ::: "memory")
#define CP_WAIT1()  asm volatile("cp.async.wait_group 1;" ::: "memory")

// ---------------- phase 0 ----------------
__global__ void zero_kernel(float* __restrict__ out, int n) {
    int i = blockIdx.x * blockDim.x + threadIdx.x;
    if (i < n) out[i] = 0.0f;
    if (blockIdx.x == 0 && threadIdx.x < NEXP) g_cnt[threadIdx.x] = 0;
}

// ---------------- x split (fp32 -> hi/lo bf16), tiny ----------------
__global__ void __launch_bounds__(256) split_kernel(
    const float4* __restrict__ src, uint2* __restrict__ hi, uint2* __restrict__ lo, int n4)
{
    int i = blockIdx.x * blockDim.x + threadIdx.x;
    if (i < n4) {
        uint2 h, l;
        split4(src[i], h, l);
        hi[i] = h;
        lo[i] = l;
    }
}

// ---------------- phase 1: router ----------------
__global__ void __launch_bounds__(128) router_kernel(
    const float* __restrict__ x, const float* __restrict__ rw)
{
    int t = blockIdx.x, tid = threadIdx.x;
    float acc[NEXP];
#pragma unroll
    for (int e = 0; e < NEXP; e++) acc[e] = 0.0f;
    const float* xr = x + (size_t)t * HID;
    for (int k = tid; k < HID; k += 128) {
        float xv = xr[k];
#pragma unroll
        for (int e = 0; e < NEXP; e++) acc[e] += xv * rw[e * HID + k];
    }
#pragma unroll
    for (int e = 0; e < NEXP; e++) {
#pragma unroll
        for (int off = 16; off > 0; off >>= 1)
            acc[e] += __shfl_down_sync(0xFFFFFFFFu, acc[e], off);
    }
    __shared__ float spart[4][NEXP];
    int warp = tid >> 5, lane = tid & 31;
    if (lane == 0) {
#pragma unroll
        for (int e = 0; e < NEXP; e++) spart[warp][e] = acc[e];
    }
    __syncthreads();
    if (tid == 0) {
        float logit[NEXP];
#pragma unroll
        for (int e = 0; e < NEXP; e++)
            logit[e] = spart[0][e] + spart[1][e] + spart[2][e] + spart[3][e];
        int idx[TOPK]; float val[TOPK]; bool used[NEXP];
#pragma unroll
        for (int e = 0; e < NEXP; e++) used[e] = false;
#pragma unroll
        for (int k = 0; k < TOPK; k++) {
            float best = -1e30f; int bi = 0;
            for (int e = 0; e < NEXP; e++)
                if (!used[e] && logit[e] > best) { best = logit[e]; bi = e; }
            used[bi] = true; idx[k] = bi; val[k] = best;
        }
        float mx = val[0], s = 0.0f, ev[TOPK];
#pragma unroll
        for (int k = 0; k < TOPK; k++) { ev[k] = expf(val[k] - mx); s += ev[k]; }
        float inv = 1.0f / s;
#pragma unroll
        for (int k = 0; k < TOPK; k++) {
            int e = idx[k];
            int pos = atomicAdd(&g_cnt[e], 1);
            g_tok[e * T_TOK + pos] = t;
            g_wt [e * T_TOK + pos] = ev[k] * inv;
        }
    }
}

// ============================================================
// GEMM smem:
//  A (128 x 32 bf16, pitch 80B): AH (10240) + AL (10240) = 20480/stage, 3 stages (cp.async)
//  gate_up B (32k x 128n bf16, pitch 272B): BH 8704 + BL 8704 = 17408/stage, 2 stages
//    (filled from fp32 weights by in-kernel LDG+split+STS)
//  down    B (32k x 64n bf16, pitch 144B): BH 4608 + BL 4608 = 9216/stage, 2 stages
// ============================================================
#define GU_A_STAGE 20480
#define GU_B_OFF   (3 * GU_A_STAGE)           // 61440
#define GU_B_STAGE 17408
#define GU_META    (GU_B_OFF + 2 * GU_B_STAGE) // 96256
#define GU_SMEM    (GU_META + 1024)            // 97280

#define DN_A_STAGE 20480
#define DN_B_OFF   (3 * DN_A_STAGE)            // 61440
#define DN_B_STAGE 9216
#define DN_META    (DN_B_OFF + 2 * DN_B_STAGE) // 79872
#define DN_SMEM    (DN_META + 1024)            // 80896

// ---------------- phase 2: gate_up GEMM ----------------
__device__ __forceinline__ void gu_loadA(
    uint32_t sb, const int* stok, int k0, int tid)
{
#pragma unroll
    for (int i = 0; i < 2; i++) {
        int c = tid + i * 256;
        int row = c >> 2, seg = c & 3;
        int tok = stok[row];
        size_t off = (size_t)tok * HID + k0 + seg * 8;
        CP16(sb + row * 80 + seg * 16,          g_xhi + off);
        CP16(sb + 10240 + row * 80 + seg * 16,  g_xlo + off);
    }
}

__global__ void __launch_bounds__(256, 2) gateup_mma(const float* __restrict__ gup)
{
    extern __shared__ char smem[];
    int e = blockIdx.z;
    int cnt = g_cnt[e];
    int mbase = blockIdx.x * 128;
    if (mbase >= cnt) return;
    int nbase = blockIdx.y * 64;

    int tid = threadIdx.x;
    int lane = tid & 31, wid = tid >> 5;
    int wm = (wid & 3) * 32;
    int wn = (wid >> 2) * 32;

    uint32_t sbase = smem_u32(smem);
    int*   stok = (int*)  (smem + GU_META);
    float* swt  = (float*)(smem + GU_META + 512);
    if (tid < 128) {
        int gm = mbase + tid;
        stok[tid] = (gm < cnt) ? g_tok[e * T_TOK + gm] : 0;
        swt[tid]  = (gm < cnt) ? g_wt [e * T_TOK + gm] : 0.0f;
    }
    __syncthreads();

    // B LDG coords for this thread (4 float4 per stage)
    int bk[4], bcol[4];
#pragma unroll
    for (int i = 0; i < 4; i++) {
        int c = tid + i * 256;
        bk[i] = c >> 5;               // 0..31
        int n = (c & 31) * 4;         // 0..124
        bcol[i] = (n < 64) ? (nbase + n) : (INTER + nbase + (n - 64));
    }

    float accG[2][4][4], accU[2][4][4];
#pragma unroll
    for (int i = 0; i < 2; i++)
#pragma unroll
        for (int j = 0; j < 4; j++)
#pragma unroll
            for (int c = 0; c < 4; c++) { accG[i][j][c] = 0.0f; accU[i][j][c] = 0.0f; }

    const int S = HID / 32;   // 64
    float4 rb[4];

    // prologue
#pragma unroll
    for (int i = 0; i < 4; i++)
        rb[i] = *reinterpret_cast<const float4*>(
            &gup[((size_t)e * HID + bk[i]) * INTER2 + bcol[i]]);
    gu_loadA(sbase, stok, 0, tid);
    CP_COMMIT();
    gu_loadA(sbase + GU_A_STAGE, stok, 32, tid);
    CP_COMMIT();
    // convert + STS B stage 0
#pragma unroll
    for (int i = 0; i < 4; i++) {
        uint2 hi, lo; split4(rb[i], hi, lo);
        int n2 = (tid + i * 256 & 31) * 8;     // n*2 bytes
        char* bp = smem + GU_B_OFF + bk[i] * 272 + n2;
        *reinterpret_cast<uint2*>(bp)        = hi;
        *reinterpret_cast<uint2*>(bp + 8704) = lo;
    }

    int a_st = 0;   // A stage of s (mod 3)
#pragma unroll 1
    for (int s = 0; s < S; s++) {
        CP_WAIT1();
        __syncthreads();
        if (s + 2 < S)
            gu_loadA(sbase + ((a_st + 2) % 3) * GU_A_STAGE, stok, (s + 2) * 32, tid);
        CP_COMMIT();
        // LDG next B stage
        if (s + 1 < S) {
            int k0n = (s + 1) * 32;
#pragma unroll
            for (int i = 0; i < 4; i++)
                rb[i] = *reinterpret_cast<const float4*>(
                    &gup[((size_t)e * HID + k0n + bk[i]) * INTER2 + bcol[i]]);
        }

        uint32_t st_a = sbase + a_st * GU_A_STAGE;
        uint32_t st_b = sbase + GU_B_OFF + (s & 1) * GU_B_STAGE;
#pragma unroll
        for (int ks = 0; ks < 2; ks++) {
            uint32_t ah[2][4], al[2][4];
#pragma unroll
            for (int mt = 0; mt < 2; mt++) {
                uint32_t aa = st_a + (wm + mt * 16 + (lane & 15)) * 80
                            + (ks * 16 + (lane >> 4) * 8) * 2;
                LDSM4(ah[mt], aa);
                LDSM4(al[mt], aa + 10240);
            }
#pragma unroll
            for (int ng = 0; ng < 2; ng++) {
                uint32_t ba = st_b + (ks * 16 + (lane & 15)) * 272
                            + (wn + ng * 16 + (lane >> 4) * 8) * 2;
                uint32_t bgh[4], bgl[4], buh[4], bul[4];
                LDSM4T(bgh, ba);
                LDSM4T(bgl, ba + 8704);
                LDSM4T(buh, ba + 128);
                LDSM4T(bul, ba + 128 + 8704);
#pragma unroll
                for (int half = 0; half < 2; half++) {
                    int j = ng * 2 + half;
#pragma unroll
                    for (int mt = 0; mt < 2; mt++) {
                        MMA_BF16(accG[mt][j], ah[mt], &bgh[half * 2]);
                        MMA_BF16(accG[mt][j], ah[mt], &bgl[half * 2]);
                        MMA_BF16(accG[mt][j], al[mt], &bgh[half * 2]);
                        MMA_BF16(accU[mt][j], ah[mt], &buh[half * 2]);
                        MMA_BF16(accU[mt][j], ah[mt], &bul[half * 2]);
                        MMA_BF16(accU[mt][j], al[mt], &buh[half * 2]);
                    }
                }
            }
        }

        // convert + STS B stage s+1 (buffer (s+1)&1; its last readers finished before top sync)
        if (s + 1 < S) {
            char* bb = smem + GU_B_OFF + ((s + 1) & 1) * GU_B_STAGE;
#pragma unroll
            for (int i = 0; i < 4; i++) {
                uint2 hi, lo; split4(rb[i], hi, lo);
                int n2 = ((tid + i * 256) & 31) * 8;
                char* bp = bb + bk[i] * 272 + n2;
                *reinterpret_cast<uint2*>(bp)        = hi;
                *reinterpret_cast<uint2*>(bp + 8704) = lo;
            }
        }
        a_st = (a_st == 2) ? 0 : a_st + 1;
    }

    // epilogue: h = silu(gate) * up * wt -> hi/lo bf16 global
#pragma unroll
    for (int mt = 0; mt < 2; mt++) {
#pragma unroll
        for (int j = 0; j < 4; j++) {
            int col = wn + (j >> 1) * 16 + (j & 1) * 8 + (lane & 3) * 2;
#pragma unroll
            for (int rh = 0; rh < 2; rh++) {
                int m = wm + mt * 16 + (lane >> 2) + rh * 8;
                int gm = mbase + m;
                if (gm >= cnt) continue;
                float w = swt[m];
                float g0 = accG[mt][j][rh * 2 + 0], u0 = accU[mt][j][rh * 2 + 0];
                float g1 = accG[mt][j][rh * 2 + 1], u1 = accU[mt][j][rh * 2 + 1];
                float h0 = (g0 / (1.0f + expf(-g0))) * u0 * w;
                float h1 = (g1 / (1.0f + expf(-g1))) * u1 * w;
                uint16_t h0h, h0l, h1h, h1l;
                split1(h0, h0h, h0l);
                split1(h1, h1h, h1l);
                size_t off = ((size_t)e * T_TOK + gm) * INTER + nbase + col;
                *reinterpret_cast<uint32_t*>(g_hhi + off) = (uint32_t)h0h | ((uint32_t)h1h << 16);
                *reinterpret_cast<uint32_t*>(g_hlo + off) = (uint32_t)h0l | ((uint32_t)h1l << 16);
            }
        }
    }
}

// ---------------- phase 3: down GEMM + atomic scatter ----------------
__device__ __forceinline__ void dn_loadA(
    uint32_t sb, int e, int mbase, int k0, int tid)
{
#pragma unroll
    for (int i = 0; i < 2; i++) {
        int c = tid + i * 256;
        int row = c >> 2, seg = c & 3;
        size_t off = ((size_t)e * T_TOK + mbase + row) * INTER + k0 + seg * 8;
        CP16(sb + row * 80 + seg * 16,         g_hhi + off);
        CP16(sb + 10240 + row * 80 + seg * 16, g_hlo + off);
    }
}

__global__ void __launch_bounds__(256, 2) down_mma(
    const float* __restrict__ dw, float* __restrict__ out)
{
    extern __shared__ char smem[];
    int e = blockIdx.z;
    int cnt = g_cnt[e];
    int mbase = blockIdx.x * 128;
    if (mbase >= cnt) return;
    int nbase = blockIdx.y * 64;

    int tid = threadIdx.x;
    int lane = tid & 31, wid = tid >> 5;
    int wm = (wid & 3) * 32;
    int wn = (wid >> 2) * 32;

    uint32_t sbase = smem_u32(smem);
    int* stok = (int*)(smem + DN_META);
    if (tid < 128) {
        int gm = mbase + tid;
        stok[tid] = (gm < cnt) ? g_tok[e * T_TOK + gm] : -1;
    }
    __syncthreads();

    // B LDG coords (2 float4 per stage)
    int bk[2], bn[2];
#pragma unroll
    for (int i = 0; i < 2; i++) {
        int c = tid + i * 256;
        bk[i] = c >> 4;              // 0..31
        bn[i] = (c & 15) * 4;        // 0..60
    }

    float acc[2][4][4];
#pragma unroll
    for (int i = 0; i < 2; i++)
#pragma unroll
        for (int j = 0; j < 4; j++)
#pragma unroll
            for (int c = 0; c < 4; c++) acc[i][j][c] = 0.0f;

    const int S = INTER / 32;  // 24
    float4 rb[2];

    // prologue
#pragma unroll
    for (int i = 0; i < 2; i++)
        rb[i] = *reinterpret_cast<const float4*>(
            &dw[((size_t)e * INTER + bk[i]) * HID + nbase + bn[i]]);
    dn_loadA(sbase, e, mbase, 0, tid);
    CP_COMMIT();
    dn_loadA(sbase + DN_A_STAGE, e, mbase, 32, tid);
    CP_COMMIT();
#pragma unroll
    for (int i = 0; i < 2; i++) {
        uint2 hi, lo; split4(rb[i], hi, lo);
        char* bp = smem + DN_B_OFF + bk[i] * 144 + bn[i] * 2;
        *reinterpret_cast<uint2*>(bp)        = hi;
        *reinterpret_cast<uint2*>(bp + 4608) = lo;
    }

    int a_st = 0;
#pragma unroll 1
    for (int s = 0; s < S; s++) {
        CP_WAIT1();
        __syncthreads();
        if (s + 2 < S)
            dn_loadA(sbase + ((a_st + 2) % 3) * DN_A_STAGE, e, mbase, (s + 2) * 32, tid);
        CP_COMMIT();
        if (s + 1 < S) {
            int k0n = (s + 1) * 32;
#pragma unroll
            for (int i = 0; i < 2; i++)
                rb[i] = *reinterpret_cast<const float4*>(
                    &dw[((size_t)e * INTER + k0n + bk[i]) * HID + nbase + bn[i]]);
        }

        uint32_t st_a = sbase + a_st * DN_A_STAGE;
        uint32_t st_b = sbase + DN_B_OFF + (s & 1) * DN_B_STAGE;
#pragma unroll
        for (int ks = 0; ks < 2; ks++) {
            uint32_t ah[2][4], al[2][4];
#pragma unroll
            for (int mt = 0; mt < 2; mt++) {
                uint32_t aa = st_a + (wm + mt * 16 + (lane & 15)) * 80
                            + (ks * 16 + (lane >> 4) * 8) * 2;
                LDSM4(ah[mt], aa);
                LDSM4(al[mt], aa + 10240);
            }
#pragma unroll
            for (int ng = 0; ng < 2; ng++) {
                uint32_t ba = st_b + (ks * 16 + (lane & 15)) * 144
                            + (wn + ng * 16 + (lane >> 4) * 8) * 2;
                uint32_t bh[4], bl2[4];
                LDSM4T(bh, ba);
                LDSM4T(bl2, ba + 4608);
#pragma unroll
                for (int half = 0; half < 2; half++) {
                    int j = ng * 2 + half;
#pragma unroll
                    for (int mt = 0; mt < 2; mt++) {
                        MMA_BF16(acc[mt][j], ah[mt], &bh[half * 2]);
                        MMA_BF16(acc[mt][j], ah[mt], &bl2[half * 2]);
                        MMA_BF16(acc[mt][j], al[mt], &bh[half * 2]);
                    }
                }
            }
        }

        if (s + 1 < S) {
            char* bb = smem + DN_B_OFF + ((s + 1) & 1) * DN_B_STAGE;
#pragma unroll
            for (int i = 0; i < 2; i++) {
                uint2 hi, lo; split4(rb[i], hi, lo);
                char* bp = bb + bk[i] * 144 + bn[i] * 2;
                *reinterpret_cast<uint2*>(bp)        = hi;
                *reinterpret_cast<uint2*>(bp + 4608) = lo;
            }
        }
        a_st = (a_st == 2) ? 0 : a_st + 1;
    }

    // epilogue: atomic scatter into out
#pragma unroll
    for (int mt = 0; mt < 2; mt++) {
#pragma unroll
        for (int rh = 0; rh < 2; rh++) {
            int m = wm + mt * 16 + (lane >> 2) + rh * 8;
            int tok = stok[m];
            if (tok < 0) continue;
            float* op = &out[(size_t)tok * HID + nbase];
#pragma unroll
            for (int j = 0; j < 4; j++) {
                int col = wn + (j >> 1) * 16 + (j & 1) * 8 + (lane & 3) * 2;
                atomicAdd(op + col,     acc[mt][j][rh * 2 + 0]);
                atomicAdd(op + col + 1, acc[mt][j][rh * 2 + 1]);
            }
        }
    }
}

// ---------------- launch ----------------
extern "C" void kernel_launch(void* const* d_in, const int* in_sizes, int n_in,
                              void* d_out, int out_size)
{
    const float* x    = (const float*)d_in[0];
    const float* rw   = (const float*)d_in[1];
    const float* gup  = (const float*)d_in[2];
    const float* dw   = (const float*)d_in[3];
    float* out = (float*)d_out;

    static bool attr_set = false;
    if (!attr_set) {
        cudaFuncSetAttribute(gateup_mma, cudaFuncAttributeMaxDynamicSharedMemorySize, GU_SMEM);
        cudaFuncSetAttribute(down_mma,   cudaFuncAttributeMaxDynamicSharedMemorySize, DN_SMEM);
        attr_set = true;
    }

    int n_out = T_TOK * HID;
    zero_kernel<<<(n_out + 511) / 512, 512>>>(out, n_out);
    router_kernel<<<T_TOK, 128>>>(x, rw);

    // x split only (8 MB — tiny)
    {
        __nv_bfloat16 *xhi, *xlo;
        cudaGetSymbolAddress((void**)&xhi, g_xhi);
        cudaGetSymbolAddress((void**)&xlo, g_xlo);
        int n4x = T_TOK * HID / 4;
        split_kernel<<<(n4x + 255) / 256, 256>>>(
            (const float4*)x, (uint2*)xhi, (uint2*)xlo, n4x);
    }

    dim3 gridG(T_TOK / 128, INTER / 64, NEXP);   // (m=8, n=12, e=16)
    gateup_mma<<<gridG, 256, GU_SMEM>>>(gup);

    dim3 gridD(T_TOK / 128, HID / 64, NEXP);     // (m=8, n=32, e=16)
    down_mma<<<gridD, 256, DN_SMEM>>>(dw, out);
}

// round 7
// speedup vs baseline: 1.6750x; 1.6750x over previous
#include <cuda_runtime.h>
#include <cuda_fp16.h>
#include <cstdint>

// Problem constants (Qwen3MoeSparseMoeBlock_2413771621126)
#define T_TOK   1024
#define HID     2048
#define NEXP    16
#define TOPK    4
#define INTER   768
#define INTER2  1536

// ---------------- device scratch (static; allocation-free) ----------------
__device__ int   g_cnt[NEXP];
__device__ int   g_tok[NEXP * T_TOK];
__device__ float g_wt [NEXP * T_TOK];

__device__ __align__(128) __half g_xh [(size_t)T_TOK * HID];
__device__ __align__(128) __half g_ghi[(size_t)NEXP * HID * INTER2];
__device__ __align__(128) __half g_glo[(size_t)NEXP * HID * INTER2];
__device__ __align__(128) __half g_dhi[(size_t)NEXP * INTER * HID];
__device__ __align__(128) __half g_dlo[(size_t)NEXP * INTER * HID];
__device__ __align__(128) __half g_hf [(size_t)NEXP * T_TOK * INTER];

// ---------------- helpers ----------------
__device__ __forceinline__ uint32_t smem_u32(const void* p) {
    uint32_t a;
    asm("{ .reg .u64 t; cvta.to.shared.u64 t, %1; cvt.u32.u64 %0, t; }" : "=r"(a) : "l"(p));
    return a;
}

// fp16 split of float4 -> hi (4 fp16 in uint2), lo (4 fp16 in uint2)
__device__ __forceinline__ void split4h(float4 f, uint2& hi, uint2& lo) {
    __half hx = __float2half(f.x);
    __half hy = __float2half(f.y);
    __half hz = __float2half(f.z);
    __half hw = __float2half(f.w);
    __half lx = __float2half(f.x - __half2float(hx));
    __half ly = __float2half(f.y - __half2float(hy));
    __half lz = __float2half(f.z - __half2float(hz));
    __half lw = __float2half(f.w - __half2float(hw));
    hi.x = ((uint32_t)__half_as_ushort(hy) << 16) | __half_as_ushort(hx);
    hi.y = ((uint32_t)__half_as_ushort(hw) << 16) | __half_as_ushort(hz);
    lo.x = ((uint32_t)__half_as_ushort(ly) << 16) | __half_as_ushort(lx);
    lo.y = ((uint32_t)__half_as_ushort(lw) << 16) | __half_as_ushort(lz);
}
// fp16 convert of float4 -> 4 fp16 (uint2)
__device__ __forceinline__ uint2 conv4h(float4 f) {
    uint2 r;
    r.x = ((uint32_t)__half_as_ushort(__float2half(f.y)) << 16) | __half_as_ushort(__float2half(f.x));
    r.y = ((uint32_t)__half_as_ushort(__float2half(f.w)) << 16) | __half_as_ushort(__float2half(f.z));
    return r;
}

#define MMA_F16(d, a, b) \
    asm volatile("mma.sync.aligned.m16n8k16.row.col.f32.f16.f16.f32 " \
        "{%0,%1,%2,%3}, {%4,%5,%6,%7}, {%8,%9}, {%0,%1,%2,%3};" \
        : "+f"((d)[0]), "+f"((d)[1]), "+f"((d)[2]), "+f"((d)[3]) \
        : "r"((a)[0]), "r"((a)[1]), "r"((a)[2]), "r"((a)[3]), \
          "r"((b)[0]), "r"((b)[1]))

#define LDSM4(r, a) \
    asm volatile("ldmatrix.sync.aligned.m8n8.x4.shared.b16 {%0,%1,%2,%3}, [%4];" \
        : "=r"((r)[0]), "=r"((r)[1]), "=r"((r)[2]), "=r"((r)[3]) : "r"(a))
#define LDSM4T(r, a) \
    asm volatile("ldmatrix.sync.aligned.m8n8.x4.trans.shared.b16 {%0,%1,%2,%3}, [%4];" \
        : "=r"((r)[0]), "=r"((r)[1]), "=r"((r)[2]), "=r"((r)[3]) : "r"(a))

#define CP16(dst, src) \
    asm volatile("cp.async.cg.shared.global [%0], [%1], 16;" \
        :: "r"(dst), "l"(__cvta_generic_to_global(src)))
#define CP_COMMIT() asm volatile("cp.async.commit_group;" ::: "memory")
#define CP_WAIT0()  asm volatile("cp.async.wait_group 0;" ::: "memory")

// ---------------- phase 0 ----------------
__global__ void zero_kernel(float* __restrict__ out, int n) {
    int i = blockIdx.x * blockDim.x + threadIdx.x;
    if (i < n) out[i] = 0.0f;
    if (blockIdx.x == 0 && threadIdx.x < NEXP) g_cnt[threadIdx.x] = 0;
}

// ---------------- weight split: fp32 -> fp16 hi/lo ----------------
__global__ void __launch_bounds__(256) splitw_kernel(
    const float4* __restrict__ src, uint2* __restrict__ hi, uint2* __restrict__ lo, int n4)
{
    int i = blockIdx.x * blockDim.x + threadIdx.x;
    if (i < n4) {
        uint2 h, l;
        split4h(src[i], h, l);
        hi[i] = h;
        lo[i] = l;
    }
}

// ---------------- x convert: fp32 -> fp16 ----------------
__global__ void __launch_bounds__(256) convx_kernel(
    const float4* __restrict__ src, uint2* __restrict__ dst, int n4)
{
    int i = blockIdx.x * blockDim.x + threadIdx.x;
    if (i < n4) dst[i] = conv4h(src[i]);
}

// ---------------- phase 1: router ----------------
__global__ void __launch_bounds__(128) router_kernel(
    const float* __restrict__ x, const float* __restrict__ rw)
{
    int t = blockIdx.x, tid = threadIdx.x;
    float acc[NEXP];
#pragma unroll
    for (int e = 0; e < NEXP; e++) acc[e] = 0.0f;
    const float* xr = x + (size_t)t * HID;
    for (int k = tid; k < HID; k += 128) {
        float xv = xr[k];
#pragma unroll
        for (int e = 0; e < NEXP; e++) acc[e] += xv * rw[e * HID + k];
    }
#pragma unroll
    for (int e = 0; e < NEXP; e++) {
#pragma unroll
        for (int off = 16; off > 0; off >>= 1)
            acc[e] += __shfl_down_sync(0xFFFFFFFFu, acc[e], off);
    }
    __shared__ float spart[4][NEXP];
    int warp = tid >> 5, lane = tid & 31;
    if (lane == 0) {
#pragma unroll
        for (int e = 0; e < NEXP; e++) spart[warp][e] = acc[e];
    }
    __syncthreads();
    if (tid == 0) {
        float logit[NEXP];
#pragma unroll
        for (int e = 0; e < NEXP; e++)
            logit[e] = spart[0][e] + spart[1][e] + spart[2][e] + spart[3][e];
        int idx[TOPK]; float val[TOPK]; bool used[NEXP];
#pragma unroll
        for (int e = 0; e < NEXP; e++) used[e] = false;
#pragma unroll
        for (int k = 0; k < TOPK; k++) {
            float best = -1e30f; int bi = 0;
            for (int e = 0; e < NEXP; e++)
                if (!used[e] && logit[e] > best) { best = logit[e]; bi = e; }
            used[bi] = true; idx[k] = bi; val[k] = best;
        }
        float mx = val[0], s = 0.0f, ev[TOPK];
#pragma unroll
        for (int k = 0; k < TOPK; k++) { ev[k] = expf(val[k] - mx); s += ev[k]; }
        float inv = 1.0f / s;
#pragma unroll
        for (int k = 0; k < TOPK; k++) {
            int e = idx[k];
            int pos = atomicAdd(&g_cnt[e], 1);
            g_tok[e * T_TOK + pos] = t;
            g_wt [e * T_TOK + pos] = ev[k] * inv;
        }
    }
}

// ============================================================
// smem (per stage, bytes):
//  A: 128 x 32 fp16, pitch 80B  -> 10240   @ 0
//  gate_up B: 32k x 128n fp16, pitch 272B: BH @ 10240 (8704), BL @ 18944 (8704)
//     stage = 27648, 2 stages = 55296, meta @ 55296
//  down B: 32k x 64n fp16, pitch 144B: BH @ 10240 (4608), BL @ 14848 (4608)
//     stage = 19456, 2 stages = 38912, meta @ 38912
// ============================================================
#define GU_STAGE 27648
#define GU_META  (2 * GU_STAGE)
#define GU_SMEM  (GU_META + 1024)
#define DN_STAGE 19456
#define DN_META  (2 * DN_STAGE)
#define DN_SMEM  (DN_META + 1024)

// ---------------- phase 2: gate_up GEMM ----------------
__device__ __forceinline__ void gu_load(
    int e, int nbase, int k0, uint32_t sb, const int* stok, int tid)
{
#pragma unroll
    for (int i = 0; i < 2; i++) {
        int c = tid + i * 256;
        int row = c >> 2, seg = c & 3;
        int tok = stok[row];
        CP16(sb + row * 80 + seg * 16, g_xh + (size_t)tok * HID + k0 + seg * 8);
    }
#pragma unroll
    for (int i = 0; i < 2; i++) {
        int c = tid + i * 256;
        int k = c >> 4, seg = c & 15;
        int n = seg * 8;
        int col = (n < 64) ? (nbase + n) : (INTER + nbase + (n - 64));
        size_t src = ((size_t)e * HID + k0 + k) * INTER2 + col;
        CP16(sb + 10240 + k * 272 + seg * 16, g_ghi + src);
        CP16(sb + 18944 + k * 272 + seg * 16, g_glo + src);
    }
}

__global__ void __launch_bounds__(256, 2) gateup_mma(int dummy)
{
    extern __shared__ char smem[];
    int e = blockIdx.z;
    int cnt = g_cnt[e];
    int mbase = blockIdx.x * 128;
    if (mbase >= cnt) return;
    int nbase = blockIdx.y * 64;

    int tid = threadIdx.x;
    int lane = tid & 31, wid = tid >> 5;
    int wm = (wid & 3) * 32;
    int wn = (wid >> 2) * 32;

    uint32_t sbase = smem_u32(smem);
    int*   stok = (int*)  (smem + GU_META);
    float* swt  = (float*)(smem + GU_META + 512);
    if (tid < 128) {
        int gm = mbase + tid;
        stok[tid] = (gm < cnt) ? g_tok[e * T_TOK + gm] : 0;
        swt[tid]  = (gm < cnt) ? g_wt [e * T_TOK + gm] : 0.0f;
    }
    __syncthreads();

    float accG[2][4][4], accU[2][4][4];
#pragma unroll
    for (int i = 0; i < 2; i++)
#pragma unroll
        for (int j = 0; j < 4; j++)
#pragma unroll
            for (int c = 0; c < 4; c++) { accG[i][j][c] = 0.0f; accU[i][j][c] = 0.0f; }

    const int S = HID / 32;   // 64
    gu_load(e, nbase, 0, sbase, stok, tid);
    CP_COMMIT();

#pragma unroll 1
    for (int s = 0; s < S; s++) {
        int b = s & 1;
        CP_WAIT0();
        __syncthreads();
        if (s + 1 < S) {
            gu_load(e, nbase, (s + 1) * 32, sbase + (b ^ 1) * GU_STAGE, stok, tid);
            CP_COMMIT();
        }
        uint32_t st = sbase + b * GU_STAGE;
#pragma unroll
        for (int ks = 0; ks < 2; ks++) {
            uint32_t a[2][4];
#pragma unroll
            for (int mt = 0; mt < 2; mt++) {
                uint32_t aa = st + (wm + mt * 16 + (lane & 15)) * 80
                            + (ks * 16 + (lane >> 4) * 8) * 2;
                LDSM4(a[mt], aa);
            }
#pragma unroll
            for (int ng = 0; ng < 2; ng++) {
                uint32_t ba = st + 10240 + (ks * 16 + (lane & 15)) * 272
                            + (wn + ng * 16 + (lane >> 4) * 8) * 2;
                uint32_t bgh[4], bgl[4], buh[4], bul[4];
                LDSM4T(bgh, ba);
                LDSM4T(bgl, ba + 8704);
                LDSM4T(buh, ba + 128);          // up cols at +64 fp16
                LDSM4T(bul, ba + 128 + 8704);
#pragma unroll
                for (int half = 0; half < 2; half++) {
                    int j = ng * 2 + half;
#pragma unroll
                    for (int mt = 0; mt < 2; mt++) {
                        MMA_F16(accG[mt][j], a[mt], &bgh[half * 2]);
                        MMA_F16(accG[mt][j], a[mt], &bgl[half * 2]);
                        MMA_F16(accU[mt][j], a[mt], &buh[half * 2]);
                        MMA_F16(accU[mt][j], a[mt], &bul[half * 2]);
                    }
                }
            }
        }
        __syncthreads();
    }

    // epilogue: h = silu(gate) * up * wt -> fp16 global
#pragma unroll
    for (int mt = 0; mt < 2; mt++) {
#pragma unroll
        for (int j = 0; j < 4; j++) {
            int col = wn + (j >> 1) * 16 + (j & 1) * 8 + (lane & 3) * 2;
#pragma unroll
            for (int rh = 0; rh < 2; rh++) {
                int m = wm + mt * 16 + (lane >> 2) + rh * 8;
                int gm = mbase + m;
                if (gm >= cnt) continue;
                float w = swt[m];
                float g0 = accG[mt][j][rh * 2 + 0], u0 = accU[mt][j][rh * 2 + 0];
                float g1 = accG[mt][j][rh * 2 + 1], u1 = accU[mt][j][rh * 2 + 1];
                float h0 = (g0 / (1.0f + expf(-g0))) * u0 * w;
                float h1 = (g1 / (1.0f + expf(-g1))) * u1 * w;
                uint32_t pk = ((uint32_t)__half_as_ushort(__float2half(h1)) << 16)
                            |  (uint32_t)__half_as_ushort(__float2half(h0));
                size_t off = ((size_t)e * T_TOK + gm) * INTER + nbase + col;
                *reinterpret_cast<uint32_t*>(g_hf + off) = pk;
            }
        }
    }
}

// ---------------- phase 3: down GEMM + atomic scatter ----------------
__device__ __forceinline__ void dn_load(
    int e, int mbase, int nbase, int k0, uint32_t sb, int tid)
{
#pragma unroll
    for (int i = 0; i < 2; i++) {
        int c = tid + i * 256;
        int row = c >> 2, seg = c & 3;
        CP16(sb + row * 80 + seg * 16,
             g_hf + ((size_t)e * T_TOK + mbase + row) * INTER + k0 + seg * 8);
    }
    {
        int k = tid >> 3, seg = tid & 7;
        size_t src = ((size_t)e * INTER + k0 + k) * HID + nbase + seg * 8;
        CP16(sb + 10240 + k * 144 + seg * 16, g_dhi + src);
        CP16(sb + 14848 + k * 144 + seg * 16, g_dlo + src);
    }
}

__global__ void __launch_bounds__(256, 2) down_mma(float* __restrict__ out)
{
    extern __shared__ char smem[];
    int e = blockIdx.z;
    int cnt = g_cnt[e];
    int mbase = blockIdx.x * 128;
    if (mbase >= cnt) return;
    int nbase = blockIdx.y * 64;

    int tid = threadIdx.x;
    int lane = tid & 31, wid = tid >> 5;
    int wm = (wid & 3) * 32;
    int wn = (wid >> 2) * 32;

    uint32_t sbase = smem_u32(smem);
    int* stok = (int*)(smem + DN_META);
    if (tid < 128) {
        int gm = mbase + tid;
        stok[tid] = (gm < cnt) ? g_tok[e * T_TOK + gm] : -1;
    }
    __syncthreads();

    float acc[2][4][4];
#pragma unroll
    for (int i = 0; i < 2; i++)
#pragma unroll
        for (int j = 0; j < 4; j++)
#pragma unroll
            for (int c = 0; c < 4; c++) acc[i][j][c] = 0.0f;

    const int S = INTER / 32;  // 24
    dn_load(e, mbase, nbase, 0, sbase, tid);
    CP_COMMIT();

#pragma unroll 1
    for (int s = 0; s < S; s++) {
        int b = s & 1;
        CP_WAIT0();
        __syncthreads();
        if (s + 1 < S) {
            dn_load(e, mbase, nbase, (s + 1) * 32, sbase + (b ^ 1) * DN_STAGE, tid);
            CP_COMMIT();
        }
        uint32_t st = sbase + b * DN_STAGE;
#pragma unroll
        for (int ks = 0; ks < 2; ks++) {
            uint32_t a[2][4];
#pragma unroll
            for (int mt = 0; mt < 2; mt++) {
                uint32_t aa = st + (wm + mt * 16 + (lane & 15)) * 80
                            + (ks * 16 + (lane >> 4) * 8) * 2;
                LDSM4(a[mt], aa);
            }
#pragma unroll
            for (int ng = 0; ng < 2; ng++) {
                uint32_t ba = st + 10240 + (ks * 16 + (lane & 15)) * 144
                            + (wn + ng * 16 + (lane >> 4) * 8) * 2;
                uint32_t bh[4], bl[4];
                LDSM4T(bh, ba);
                LDSM4T(bl, ba + 4608);
#pragma unroll
                for (int half = 0; half < 2; half++) {
                    int j = ng * 2 + half;
#pragma unroll
                    for (int mt = 0; mt < 2; mt++) {
                        MMA_F16(acc[mt][j], a[mt], &bh[half * 2]);
                        MMA_F16(acc[mt][j], a[mt], &bl[half * 2]);
                    }
                }
            }
        }
        __syncthreads();
    }

    // epilogue: atomic scatter into out
#pragma unroll
    for (int mt = 0; mt < 2; mt++) {
#pragma unroll
        for (int rh = 0; rh < 2; rh++) {
            int m = wm + mt * 16 + (lane >> 2) + rh * 8;
            int tok = stok[m];
            if (tok < 0) continue;
            float* op = &out[(size_t)tok * HID + nbase];
#pragma unroll
            for (int j = 0; j < 4; j++) {
                int col = wn + (j >> 1) * 16 + (j & 1) * 8 + (lane & 3) * 2;
                atomicAdd(op + col,     acc[mt][j][rh * 2 + 0]);
                atomicAdd(op + col + 1, acc[mt][j][rh * 2 + 1]);
            }
        }
    }
}

// ---------------- launch ----------------
extern "C" void kernel_launch(void* const* d_in, const int* in_sizes, int n_in,
                              void* d_out, int out_size)
{
    const float* x    = (const float*)d_in[0];
    const float* rw   = (const float*)d_in[1];
    const float* gup  = (const float*)d_in[2];
    const float* dw   = (const float*)d_in[3];
    float* out = (float*)d_out;

    static bool attr_set = false;
    if (!attr_set) {
        cudaFuncSetAttribute(gateup_mma, cudaFuncAttributeMaxDynamicSharedMemorySize, GU_SMEM);
        cudaFuncSetAttribute(down_mma,   cudaFuncAttributeMaxDynamicSharedMemorySize, DN_SMEM);
        attr_set = true;
    }

    int n_out = T_TOK * HID;
    zero_kernel<<<(n_out + 511) / 512, 512>>>(out, n_out);
    router_kernel<<<T_TOK, 128>>>(x, rw);

    // conversions
    {
        __half *xh, *ghi, *glo, *dhi, *dlo;
        cudaGetSymbolAddress((void**)&xh,  g_xh);
        cudaGetSymbolAddress((void**)&ghi, g_ghi);
        cudaGetSymbolAddress((void**)&glo, g_glo);
        cudaGetSymbolAddress((void**)&dhi, g_dhi);
        cudaGetSymbolAddress((void**)&dlo, g_dlo);

        int n4x = T_TOK * HID / 4;
        convx_kernel<<<(n4x + 255) / 256, 256>>>(
            (const float4*)x, (uint2*)xh, n4x);
        int n4g = NEXP * HID * INTER2 / 4;
        splitw_kernel<<<(n4g + 255) / 256, 256>>>(
            (const float4*)gup, (uint2*)ghi, (uint2*)glo, n4g);
        int n4d = NEXP * INTER * HID / 4;
        splitw_kernel<<<(n4d + 255) / 256, 256>>>(
            (const float4*)dw, (uint2*)dhi, (uint2*)dlo, n4d);
    }

    dim3 gridG(T_TOK / 128, INTER / 64, NEXP);   // (m=8, n=12, e=16)
    gateup_mma<<<gridG, 256, GU_SMEM>>>(0);

    dim3 gridD(T_TOK / 128, HID / 64, NEXP);     // (m=8, n=32, e=16)
    down_mma<<<gridD, 256, DN_SMEM>>>(out);
}

// round 8
// speedup vs baseline: 1.9986x; 1.1932x over previous
#include <cuda_runtime.h>
#include <cuda_fp16.h>
#include <cstdint>

// Problem constants (Qwen3MoeSparseMoeBlock_2413771621126)
#define T_TOK   1024
#define HID     2048
#define NEXP    16
#define TOPK    4
#define INTER   768
#define INTER2  1536

// ---------------- device scratch (static; allocation-free) ----------------
__device__ int   g_cnt[NEXP];
__device__ int   g_tok[NEXP * T_TOK];
__device__ float g_wt [NEXP * T_TOK];

__device__ __align__(128) __half g_xh[(size_t)T_TOK * HID];
__device__ __align__(128) __half g_gh[(size_t)NEXP * HID * INTER2];
__device__ __align__(128) __half g_dh[(size_t)NEXP * INTER * HID];
__device__ __align__(128) __half g_hf[(size_t)NEXP * T_TOK * INTER];

// ---------------- helpers ----------------
__device__ __forceinline__ uint32_t smem_u32(const void* p) {
    uint32_t a;
    asm("{ .reg .u64 t; cvta.to.shared.u64 t, %1; cvt.u32.u64 %0, t; }" : "=r"(a) : "l"(p));
    return a;
}

// fp16 convert of float4 -> 4 fp16 (uint2)
__device__ __forceinline__ uint2 conv4h(float4 f) {
    uint2 r;
    r.x = ((uint32_t)__half_as_ushort(__float2half(f.y)) << 16) | __half_as_ushort(__float2half(f.x));
    r.y = ((uint32_t)__half_as_ushort(__float2half(f.w)) << 16) | __half_as_ushort(__float2half(f.z));
    return r;
}

#define MMA_F16(d, a, b) \
    asm volatile("mma.sync.aligned.m16n8k16.row.col.f32.f16.f16.f32 " \
        "{%0,%1,%2,%3}, {%4,%5,%6,%7}, {%8,%9}, {%0,%1,%2,%3};" \
        : "+f"((d)[0]), "+f"((d)[1]), "+f"((d)[2]), "+f"((d)[3]) \
        : "r"((a)[0]), "r"((a)[1]), "r"((a)[2]), "r"((a)[3]), \
          "r"((b)[0]), "r"((b)[1]))

#define LDSM4(r, a) \
    asm volatile("ldmatrix.sync.aligned.m8n8.x4.shared.b16 {%0,%1,%2,%3}, [%4];" \
        : "=r"((r)[0]), "=r"((r)[1]), "=r"((r)[2]), "=r"((r)[3]) : "r"(a))
#define LDSM4T(r, a) \
    asm volatile("ldmatrix.sync.aligned.m8n8.x4.trans.shared.b16 {%0,%1,%2,%3}, [%4];" \
        : "=r"((r)[0]), "=r"((r)[1]), "=r"((r)[2]), "=r"((r)[3]) : "r"(a))

#define CP16(dst, src) \
    asm volatile("cp.async.cg.shared.global [%0], [%1], 16;" \
        :: "r"(dst), "l"(__cvta_generic_to_global(src)))
#define CP_COMMIT() asm volatile("cp.async.commit_group;" ::: "memory")
#define CP_WAIT0()  asm volatile("cp.async.wait_group 0;" ::: "memory")

// ---------------- phase 0 ----------------
__global__ void zero_kernel(float* __restrict__ out, int n) {
    int i = blockIdx.x * blockDim.x + threadIdx.x;
    if (i < n) out[i] = 0.0f;
    if (blockIdx.x == 0 && threadIdx.x < NEXP) g_cnt[threadIdx.x] = 0;
}

// ---------------- fp32 -> fp16 convert ----------------
__global__ void __launch_bounds__(256) convh_kernel(
    const float4* __restrict__ src, uint2* __restrict__ dst, int n4)
{
    int i = blockIdx.x * blockDim.x + threadIdx.x;
    if (i < n4) dst[i] = conv4h(src[i]);
}

// ---------------- phase 1: router ----------------
__global__ void __launch_bounds__(128) router_kernel(
    const float* __restrict__ x, const float* __restrict__ rw)
{
    int t = blockIdx.x, tid = threadIdx.x;
    float acc[NEXP];
#pragma unroll
    for (int e = 0; e < NEXP; e++) acc[e] = 0.0f;
    const float* xr = x + (size_t)t * HID;
    for (int k = tid; k < HID; k += 128) {
        float xv = xr[k];
#pragma unroll
        for (int e = 0; e < NEXP; e++) acc[e] += xv * rw[e * HID + k];
    }
#pragma unroll
    for (int e = 0; e < NEXP; e++) {
#pragma unroll
        for (int off = 16; off > 0; off >>= 1)
            acc[e] += __shfl_down_sync(0xFFFFFFFFu, acc[e], off);
    }
    __shared__ float spart[4][NEXP];
    int warp = tid >> 5, lane = tid & 31;
    if (lane == 0) {
#pragma unroll
        for (int e = 0; e < NEXP; e++) spart[warp][e] = acc[e];
    }
    __syncthreads();
    if (tid == 0) {
        float logit[NEXP];
#pragma unroll
        for (int e = 0; e < NEXP; e++)
            logit[e] = spart[0][e] + spart[1][e] + spart[2][e] + spart[3][e];
        int idx[TOPK]; float val[TOPK]; bool used[NEXP];
#pragma unroll
        for (int e = 0; e < NEXP; e++) used[e] = false;
#pragma unroll
        for (int k = 0; k < TOPK; k++) {
            float best = -1e30f; int bi = 0;
            for (int e = 0; e < NEXP; e++)
                if (!used[e] && logit[e] > best) { best = logit[e]; bi = e; }
            used[bi] = true; idx[k] = bi; val[k] = best;
        }
        float mx = val[0], s = 0.0f, ev[TOPK];
#pragma unroll
        for (int k = 0; k < TOPK; k++) { ev[k] = expf(val[k] - mx); s += ev[k]; }
        float inv = 1.0f / s;
#pragma unroll
        for (int k = 0; k < TOPK; k++) {
            int e = idx[k];
            int pos = atomicAdd(&g_cnt[e], 1);
            g_tok[e * T_TOK + pos] = t;
            g_wt [e * T_TOK + pos] = ev[k] * inv;
        }
    }
}

// ============================================================
// smem (per stage, bytes):
//  A: 128 x 32 fp16, pitch 80B  -> 10240 @ 0
//  gate_up B: 32k x 128n fp16, pitch 272B -> 8704 @ 10240 ; stage 18944
//  down    B: 32k x  64n fp16, pitch 144B -> 4608 @ 10240 ; stage 14848
// ============================================================
#define GU_STAGE 18944
#define GU_META  (2 * GU_STAGE)
#define GU_SMEM  (GU_META + 1024)
#define DN_STAGE 14848
#define DN_META  (2 * DN_STAGE)
#define DN_SMEM  (DN_META + 1024)

// ---------------- phase 2: gate_up GEMM ----------------
__device__ __forceinline__ void gu_load(
    int e, int nbase, int k0, uint32_t sb, const int* stok, int tid)
{
#pragma unroll
    for (int i = 0; i < 2; i++) {
        int c = tid + i * 256;
        int row = c >> 2, seg = c & 3;
        int tok = stok[row];
        CP16(sb + row * 80 + seg * 16, g_xh + (size_t)tok * HID + k0 + seg * 8);
    }
#pragma unroll
    for (int i = 0; i < 2; i++) {
        int c = tid + i * 256;
        int k = c >> 4, seg = c & 15;
        int n = seg * 8;
        int col = (n < 64) ? (nbase + n) : (INTER + nbase + (n - 64));
        CP16(sb + 10240 + k * 272 + seg * 16,
             g_gh + ((size_t)e * HID + k0 + k) * INTER2 + col);
    }
}

__global__ void __launch_bounds__(256, 2) gateup_mma(int dummy)
{
    extern __shared__ char smem[];
    int e = blockIdx.z;
    int cnt = g_cnt[e];
    int mbase = blockIdx.x * 128;
    if (mbase >= cnt) return;
    int nbase = blockIdx.y * 64;

    int tid = threadIdx.x;
    int lane = tid & 31, wid = tid >> 5;
    int wm = (wid & 3) * 32;
    int wn = (wid >> 2) * 32;

    uint32_t sbase = smem_u32(smem);
    int*   stok = (int*)  (smem + GU_META);
    float* swt  = (float*)(smem + GU_META + 512);
    if (tid < 128) {
        int gm = mbase + tid;
        stok[tid] = (gm < cnt) ? g_tok[e * T_TOK + gm] : 0;
        swt[tid]  = (gm < cnt) ? g_wt [e * T_TOK + gm] : 0.0f;
    }
    __syncthreads();

    float accG[2][4][4], accU[2][4][4];
#pragma unroll
    for (int i = 0; i < 2; i++)
#pragma unroll
        for (int j = 0; j < 4; j++)
#pragma unroll
            for (int c = 0; c < 4; c++) { accG[i][j][c] = 0.0f; accU[i][j][c] = 0.0f; }

    const int S = HID / 32;   // 64
    gu_load(e, nbase, 0, sbase, stok, tid);
    CP_COMMIT();

#pragma unroll 1
    for (int s = 0; s < S; s++) {
        int b = s & 1;
        CP_WAIT0();
        __syncthreads();
        if (s + 1 < S) {
            gu_load(e, nbase, (s + 1) * 32, sbase + (b ^ 1) * GU_STAGE, stok, tid);
            CP_COMMIT();
        }
        uint32_t st = sbase + b * GU_STAGE;
#pragma unroll
        for (int ks = 0; ks < 2; ks++) {
            uint32_t a[2][4];
#pragma unroll
            for (int mt = 0; mt < 2; mt++) {
                uint32_t aa = st + (wm + mt * 16 + (lane & 15)) * 80
                            + (ks * 16 + (lane >> 4) * 8) * 2;
                LDSM4(a[mt], aa);
            }
#pragma unroll
            for (int ng = 0; ng < 2; ng++) {
                uint32_t ba = st + 10240 + (ks * 16 + (lane & 15)) * 272
                            + (wn + ng * 16 + (lane >> 4) * 8) * 2;
                uint32_t bg[4], bu[4];
                LDSM4T(bg, ba);
                LDSM4T(bu, ba + 128);           // up cols at +64 fp16
#pragma unroll
                for (int half = 0; half < 2; half++) {
                    int j = ng * 2 + half;
#pragma unroll
                    for (int mt = 0; mt < 2; mt++) {
                        MMA_F16(accG[mt][j], a[mt], &bg[half * 2]);
                        MMA_F16(accU[mt][j], a[mt], &bu[half * 2]);
                    }
                }
            }
        }
        __syncthreads();
    }

    // epilogue: h = silu(gate) * up * wt -> fp16 global
#pragma unroll
    for (int mt = 0; mt < 2; mt++) {
#pragma unroll
        for (int j = 0; j < 4; j++) {
            int col = wn + (j >> 1) * 16 + (j & 1) * 8 + (lane & 3) * 2;
#pragma unroll
            for (int rh = 0; rh < 2; rh++) {
                int m = wm + mt * 16 + (lane >> 2) + rh * 8;
                int gm = mbase + m;
                if (gm >= cnt) continue;
                float w = swt[m];
                float g0 = accG[mt][j][rh * 2 + 0], u0 = accU[mt][j][rh * 2 + 0];
                float g1 = accG[mt][j][rh * 2 + 1], u1 = accU[mt][j][rh * 2 + 1];
                float h0 = (g0 / (1.0f + expf(-g0))) * u0 * w;
                float h1 = (g1 / (1.0f + expf(-g1))) * u1 * w;
                uint32_t pk = ((uint32_t)__half_as_ushort(__float2half(h1)) << 16)
                            |  (uint32_t)__half_as_ushort(__float2half(h0));
                size_t off = ((size_t)e * T_TOK + gm) * INTER + nbase + col;
                *reinterpret_cast<uint32_t*>(g_hf + off) = pk;
            }
        }
    }
}

// ---------------- phase 3: down GEMM + atomic scatter ----------------
__device__ __forceinline__ void dn_load(
    int e, int mbase, int nbase, int k0, uint32_t sb, int tid)
{
#pragma unroll
    for (int i = 0; i < 2; i++) {
        int c = tid + i * 256;
        int row = c >> 2, seg = c & 3;
        CP16(sb + row * 80 + seg * 16,
             g_hf + ((size_t)e * T_TOK + mbase + row) * INTER + k0 + seg * 8);
    }
    {
        int k = tid >> 3, seg = tid & 7;
        CP16(sb + 10240 + k * 144 + seg * 16,
             g_dh + ((size_t)e * INTER + k0 + k) * HID + nbase + seg * 8);
    }
}

__global__ void __launch_bounds__(256, 2) down_mma(float* __restrict__ out)
{
    extern __shared__ char smem[];
    int e = blockIdx.z;
    int cnt = g_cnt[e];
    int mbase = blockIdx.x * 128;
    if (mbase >= cnt) return;
    int nbase = blockIdx.y * 64;

    int tid = threadIdx.x;
    int lane = tid & 31, wid = tid >> 5;
    int wm = (wid & 3) * 32;
    int wn = (wid >> 2) * 32;

    uint32_t sbase = smem_u32(smem);
    int* stok = (int*)(smem + DN_META);
    if (tid < 128) {
        int gm = mbase + tid;
        stok[tid] = (gm < cnt) ? g_tok[e * T_TOK + gm] : -1;
    }
    __syncthreads();

    float acc[2][4][4];
#pragma unroll
    for (int i = 0; i < 2; i++)
#pragma unroll
        for (int j = 0; j < 4; j++)
#pragma unroll
            for (int c = 0; c < 4; c++) acc[i][j][c] = 0.0f;

    const int S = INTER / 32;  // 24
    dn_load(e, mbase, nbase, 0, sbase, tid);
    CP_COMMIT();

#pragma unroll 1
    for (int s = 0; s < S; s++) {
        int b = s & 1;
        CP_WAIT0();
        __syncthreads();
        if (s + 1 < S) {
            dn_load(e, mbase, nbase, (s + 1) * 32, sbase + (b ^ 1) * DN_STAGE, tid);
            CP_COMMIT();
        }
        uint32_t st = sbase + b * DN_STAGE;
#pragma unroll
        for (int ks = 0; ks < 2; ks++) {
            uint32_t a[2][4];
#pragma unroll
            for (int mt = 0; mt < 2; mt++) {
                uint32_t aa = st + (wm + mt * 16 + (lane & 15)) * 80
                            + (ks * 16 + (lane >> 4) * 8) * 2;
                LDSM4(a[mt], aa);
            }
#pragma unroll
            for (int ng = 0; ng < 2; ng++) {
                uint32_t ba = st + 10240 + (ks * 16 + (lane & 15)) * 144
                            + (wn + ng * 16 + (lane >> 4) * 8) * 2;
                uint32_t bh[4];
                LDSM4T(bh, ba);
#pragma unroll
                for (int half = 0; half < 2; half++) {
                    int j = ng * 2 + half;
#pragma unroll
                    for (int mt = 0; mt < 2; mt++)
                        MMA_F16(acc[mt][j], a[mt], &bh[half * 2]);
                }
            }
        }
        __syncthreads();
    }

    // epilogue: atomic scatter into out
#pragma unroll
    for (int mt = 0; mt < 2; mt++) {
#pragma unroll
        for (int rh = 0; rh < 2; rh++) {
            int m = wm + mt * 16 + (lane >> 2) + rh * 8;
            int tok = stok[m];
            if (tok < 0) continue;
            float* op = &out[(size_t)tok * HID + nbase];
#pragma unroll
            for (int j = 0; j < 4; j++) {
                int col = wn + (j >> 1) * 16 + (j & 1) * 8 + (lane & 3) * 2;
                atomicAdd(op + col,     acc[mt][j][rh * 2 + 0]);
                atomicAdd(op + col + 1, acc[mt][j][rh * 2 + 1]);
            }
        }
    }
}

// ---------------- launch ----------------
extern "C" void kernel_launch(void* const* d_in, const int* in_sizes, int n_in,
                              void* d_out, int out_size)
{
    const float* x    = (const float*)d_in[0];
    const float* rw   = (const float*)d_in[1];
    const float* gup  = (const float*)d_in[2];
    const float* dw   = (const float*)d_in[3];
    float* out = (float*)d_out;

    static bool attr_set = false;
    if (!attr_set) {
        cudaFuncSetAttribute(gateup_mma, cudaFuncAttributeMaxDynamicSharedMemorySize, GU_SMEM);
        cudaFuncSetAttribute(down_mma,   cudaFuncAttributeMaxDynamicSharedMemorySize, DN_SMEM);
        attr_set = true;
    }

    int n_out = T_TOK * HID;
    zero_kernel<<<(n_out + 511) / 512, 512>>>(out, n_out);
    router_kernel<<<T_TOK, 128>>>(x, rw);

    // conversions (fp32 -> fp16)
    {
        __half *xh, *gh, *dh;
        cudaGetSymbolAddress((void**)&xh, g_xh);
        cudaGetSymbolAddress((void**)&gh, g_gh);
        cudaGetSymbolAddress((void**)&dh, g_dh);

        int n4x = T_TOK * HID / 4;
        convh_kernel<<<(n4x + 255) / 256, 256>>>(
            (const float4*)x, (uint2*)xh, n4x);
        int n4g = NEXP * HID * INTER2 / 4;
        convh_kernel<<<(n4g + 255) / 256, 256>>>(
            (const float4*)gup, (uint2*)gh, n4g);
        int n4d = NEXP * INTER * HID / 4;
        convh_kernel<<<(n4d + 255) / 256, 256>>>(
            (const float4*)dw, (uint2*)dh, n4d);
    }

    dim3 gridG(T_TOK / 128, INTER / 64, NEXP);   // (m=8, n=12, e=16)
    gateup_mma<<<gridG, 256, GU_SMEM>>>(0);

    dim3 gridD(T_TOK / 128, HID / 64, NEXP);     // (m=8, n=32, e=16)
    down_mma<<<gridD, 256, DN_SMEM>>>(out);
}

// round 9
// speedup vs baseline: 2.2330x; 1.1173x over previous
#include <cuda_runtime.h>
#include <cuda_fp16.h>
#include <cstdint>

// Problem constants (Qwen3MoeSparseMoeBlock_2413771621126)
#define T_TOK   1024
#define HID     2048
#define NEXP    16
#define TOPK    4
#define INTER   768
#define INTER2  1536

// ---------------- device scratch (static; allocation-free) ----------------
__device__ int   g_cnt[NEXP];
__device__ int   g_tok[NEXP * T_TOK];
__device__ float g_wt [NEXP * T_TOK];

__device__ __align__(128) __half g_xh[(size_t)T_TOK * HID];
__device__ __align__(128) __half g_gh[(size_t)NEXP * HID * INTER2];
__device__ __align__(128) __half g_dh[(size_t)NEXP * INTER * HID];
__device__ __align__(128) __half g_hf[(size_t)NEXP * T_TOK * INTER];

// ---------------- helpers ----------------
__device__ __forceinline__ uint32_t smem_u32(const void* p) {
    uint32_t a;
    asm("{ .reg .u64 t; cvta.to.shared.u64 t, %1; cvt.u32.u64 %0, t; }" : "=r"(a) : "l"(p));
    return a;
}

// fp16 convert of float4 -> 4 fp16 (uint2)
__device__ __forceinline__ uint2 conv4h(float4 f) {
    uint2 r;
    r.x = ((uint32_t)__half_as_ushort(__float2half(f.y)) << 16) | __half_as_ushort(__float2half(f.x));
    r.y = ((uint32_t)__half_as_ushort(__float2half(f.w)) << 16) | __half_as_ushort(__float2half(f.z));
    return r;
}

#define MMA_F16(d, a, b) \
    asm volatile("mma.sync.aligned.m16n8k16.row.col.f32.f16.f16.f32 " \
        "{%0,%1,%2,%3}, {%4,%5,%6,%7}, {%8,%9}, {%0,%1,%2,%3};" \
        : "+f"((d)[0]), "+f"((d)[1]), "+f"((d)[2]), "+f"((d)[3]) \
        : "r"((a)[0]), "r"((a)[1]), "r"((a)[2]), "r"((a)[3]), \
          "r"((b)[0]), "r"((b)[1]))

#define LDSM4(r, a) \
    asm volatile("ldmatrix.sync.aligned.m8n8.x4.shared.b16 {%0,%1,%2,%3}, [%4];" \
        : "=r"((r)[0]), "=r"((r)[1]), "=r"((r)[2]), "=r"((r)[3]) : "r"(a))
#define LDSM4T(r, a) \
    asm volatile("ldmatrix.sync.aligned.m8n8.x4.trans.shared.b16 {%0,%1,%2,%3}, [%4];" \
        : "=r"((r)[0]), "=r"((r)[1]), "=r"((r)[2]), "=r"((r)[3]) : "r"(a))

#define CP16(dst, src) \
    asm volatile("cp.async.cg.shared.global [%0], [%1], 16;" \
        :: "r"(dst), "l"(__cvta_generic_to_global(src)))
#define CP_COMMIT() asm volatile("cp.async.commit_group;" ::: "memory")
#define CP_WAIT2()  asm volatile("cp.async.wait_group 2;" ::: "memory")

// ---------------- phase 0 ----------------
__global__ void zero_kernel(float* __restrict__ out, int n) {
    int i = blockIdx.x * blockDim.x + threadIdx.x;
    if (i < n) out[i] = 0.0f;
    if (blockIdx.x == 0 && threadIdx.x < NEXP) g_cnt[threadIdx.x] = 0;
}

// ---------------- fp32 -> fp16 convert ----------------
__global__ void __launch_bounds__(256) convh_kernel(
    const float4* __restrict__ src, uint2* __restrict__ dst, int n4)
{
    int i = blockIdx.x * blockDim.x + threadIdx.x;
    if (i < n4) dst[i] = conv4h(src[i]);
}

// ---------------- phase 1: router ----------------
__global__ void __launch_bounds__(128) router_kernel(
    const float* __restrict__ x, const float* __restrict__ rw)
{
    int t = blockIdx.x, tid = threadIdx.x;
    float acc[NEXP];
#pragma unroll
    for (int e = 0; e < NEXP; e++) acc[e] = 0.0f;
    const float* xr = x + (size_t)t * HID;
    for (int k = tid; k < HID; k += 128) {
        float xv = xr[k];
#pragma unroll
        for (int e = 0; e < NEXP; e++) acc[e] += xv * rw[e * HID + k];
    }
#pragma unroll
    for (int e = 0; e < NEXP; e++) {
#pragma unroll
        for (int off = 16; off > 0; off >>= 1)
            acc[e] += __shfl_down_sync(0xFFFFFFFFu, acc[e], off);
    }
    __shared__ float spart[4][NEXP];
    int warp = tid >> 5, lane = tid & 31;
    if (lane == 0) {
#pragma unroll
        for (int e = 0; e < NEXP; e++) spart[warp][e] = acc[e];
    }
    __syncthreads();
    if (tid == 0) {
        float logit[NEXP];
#pragma unroll
        for (int e = 0; e < NEXP; e++)
            logit[e] = spart[0][e] + spart[1][e] + spart[2][e] + spart[3][e];
        int idx[TOPK]; float val[TOPK]; bool used[NEXP];
#pragma unroll
        for (int e = 0; e < NEXP; e++) used[e] = false;
#pragma unroll
        for (int k = 0; k < TOPK; k++) {
            float best = -1e30f; int bi = 0;
            for (int e = 0; e < NEXP; e++)
                if (!used[e] && logit[e] > best) { best = logit[e]; bi = e; }
            used[bi] = true; idx[k] = bi; val[k] = best;
        }
        float mx = val[0], s = 0.0f, ev[TOPK];
#pragma unroll
        for (int k = 0; k < TOPK; k++) { ev[k] = expf(val[k] - mx); s += ev[k]; }
        float inv = 1.0f / s;
#pragma unroll
        for (int k = 0; k < TOPK; k++) {
            int e = idx[k];
            int pos = atomicAdd(&g_cnt[e], 1);
            g_tok[e * T_TOK + pos] = t;
            g_wt [e * T_TOK + pos] = ev[k] * inv;
        }
    }
}

// ============================================================
// smem (per stage, bytes), 4-stage cp.async ring:
//  A: 128 x 32 fp16, pitch 80B  -> 10240 @ 0
//  gate_up B: 32k x 128n fp16, pitch 272B -> 8704 @ 10240 ; stage 18944
//  down    B: 32k x  64n fp16, pitch 144B -> 4608 @ 10240 ; stage 14848
// ============================================================
#define GU_STAGE 18944
#define GU_META  (4 * GU_STAGE)
#define GU_SMEM  (GU_META + 1024)
#define DN_STAGE 14848
#define DN_META  (4 * DN_STAGE)
#define DN_SMEM  (DN_META + 1024)

// ---------------- phase 2: gate_up GEMM ----------------
__device__ __forceinline__ void gu_load(
    int e, int nbase, int k0, uint32_t sb, const int* stok, int tid)
{
#pragma unroll
    for (int i = 0; i < 2; i++) {
        int c = tid + i * 256;
        int row = c >> 2, seg = c & 3;
        int tok = stok[row];
        CP16(sb + row * 80 + seg * 16, g_xh + (size_t)tok * HID + k0 + seg * 8);
    }
#pragma unroll
    for (int i = 0; i < 2; i++) {
        int c = tid + i * 256;
        int k = c >> 4, seg = c & 15;
        int n = seg * 8;
        int col = (n < 64) ? (nbase + n) : (INTER + nbase + (n - 64));
        CP16(sb + 10240 + k * 272 + seg * 16,
             g_gh + ((size_t)e * HID + k0 + k) * INTER2 + col);
    }
}

__global__ void __launch_bounds__(256, 2) gateup_mma(int dummy)
{
    extern __shared__ char smem[];
    int e = blockIdx.z;
    int cnt = g_cnt[e];
    int mbase = blockIdx.x * 128;
    if (mbase >= cnt) return;
    int nbase = blockIdx.y * 64;

    int tid = threadIdx.x;
    int lane = tid & 31, wid = tid >> 5;
    int wm = (wid & 3) * 32;
    int wn = (wid >> 2) * 32;

    uint32_t sbase = smem_u32(smem);
    int*   stok = (int*)  (smem + GU_META);
    float* swt  = (float*)(smem + GU_META + 512);
    if (tid < 128) {
        int gm = mbase + tid;
        stok[tid] = (gm < cnt) ? g_tok[e * T_TOK + gm] : 0;
        swt[tid]  = (gm < cnt) ? g_wt [e * T_TOK + gm] : 0.0f;
    }
    __syncthreads();

    float accG[2][4][4], accU[2][4][4];
#pragma unroll
    for (int i = 0; i < 2; i++)
#pragma unroll
        for (int j = 0; j < 4; j++)
#pragma unroll
            for (int c = 0; c < 4; c++) { accG[i][j][c] = 0.0f; accU[i][j][c] = 0.0f; }

    const int S = HID / 32;   // 64
    gu_load(e, nbase, 0,  sbase,                stok, tid); CP_COMMIT();
    gu_load(e, nbase, 32, sbase + GU_STAGE,     stok, tid); CP_COMMIT();
    gu_load(e, nbase, 64, sbase + 2 * GU_STAGE, stok, tid); CP_COMMIT();

#pragma unroll 1
    for (int s = 0; s < S; s++) {
        CP_WAIT2();
        __syncthreads();
        if (s + 3 < S)
            gu_load(e, nbase, (s + 3) * 32, sbase + ((s + 3) & 3) * GU_STAGE, stok, tid);
        CP_COMMIT();

        uint32_t st = sbase + (s & 3) * GU_STAGE;
#pragma unroll
        for (int ks = 0; ks < 2; ks++) {
            uint32_t a[2][4];
#pragma unroll
            for (int mt = 0; mt < 2; mt++) {
                uint32_t aa = st + (wm + mt * 16 + (lane & 15)) * 80
                            + (ks * 16 + (lane >> 4) * 8) * 2;
                LDSM4(a[mt], aa);
            }
#pragma unroll
            for (int ng = 0; ng < 2; ng++) {
                uint32_t ba = st + 10240 + (ks * 16 + (lane & 15)) * 272
                            + (wn + ng * 16 + (lane >> 4) * 8) * 2;
                uint32_t bg[4], bu[4];
                LDSM4T(bg, ba);
                LDSM4T(bu, ba + 128);           // up cols at +64 fp16
#pragma unroll
                for (int half = 0; half < 2; half++) {
                    int j = ng * 2 + half;
#pragma unroll
                    for (int mt = 0; mt < 2; mt++) {
                        MMA_F16(accG[mt][j], a[mt], &bg[half * 2]);
                        MMA_F16(accU[mt][j], a[mt], &bu[half * 2]);
                    }
                }
            }
        }
    }

    // epilogue: h = silu(gate) * up * wt -> fp16 global
#pragma unroll
    for (int mt = 0; mt < 2; mt++) {
#pragma unroll
        for (int j = 0; j < 4; j++) {
            int col = wn + (j >> 1) * 16 + (j & 1) * 8 + (lane & 3) * 2;
#pragma unroll
            for (int rh = 0; rh < 2; rh++) {
                int m = wm + mt * 16 + (lane >> 2) + rh * 8;
                int gm = mbase + m;
                if (gm >= cnt) continue;
                float w = swt[m];
                float g0 = accG[mt][j][rh * 2 + 0], u0 = accU[mt][j][rh * 2 + 0];
                float g1 = accG[mt][j][rh * 2 + 1], u1 = accU[mt][j][rh * 2 + 1];
                float h0 = (g0 / (1.0f + expf(-g0))) * u0 * w;
                float h1 = (g1 / (1.0f + expf(-g1))) * u1 * w;
                uint32_t pk = ((uint32_t)__half_as_ushort(__float2half(h1)) << 16)
                            |  (uint32_t)__half_as_ushort(__float2half(h0));
                size_t off = ((size_t)e * T_TOK + gm) * INTER + nbase + col;
                *reinterpret_cast<uint32_t*>(g_hf + off) = pk;
            }
        }
    }
}

// ---------------- phase 3: down GEMM + atomic scatter ----------------
__device__ __forceinline__ void dn_load(
    int e, int mbase, int nbase, int k0, uint32_t sb, int tid)
{
#pragma unroll
    for (int i = 0; i < 2; i++) {
        int c = tid + i * 256;
        int row = c >> 2, seg = c & 3;
        CP16(sb + row * 80 + seg * 16,
             g_hf + ((size_t)e * T_TOK + mbase + row) * INTER + k0 + seg * 8);
    }
    {
        int k = tid >> 3, seg = tid & 7;
        CP16(sb + 10240 + k * 144 + seg * 16,
             g_dh + ((size_t)e * INTER + k0 + k) * HID + nbase + seg * 8);
    }
}

__global__ void __launch_bounds__(256, 2) down_mma(float* __restrict__ out)
{
    extern __shared__ char smem[];
    int e = blockIdx.z;
    int cnt = g_cnt[e];
    int mbase = blockIdx.x * 128;
    if (mbase >= cnt) return;
    int nbase = blockIdx.y * 64;

    int tid = threadIdx.x;
    int lane = tid & 31, wid = tid >> 5;
    int wm = (wid & 3) * 32;
    int wn = (wid >> 2) * 32;

    uint32_t sbase = smem_u32(smem);
    int* stok = (int*)(smem + DN_META);
    if (tid < 128) {
        int gm = mbase + tid;
        stok[tid] = (gm < cnt) ? g_tok[e * T_TOK + gm] : -1;
    }
    __syncthreads();

    float acc[2][4][4];
#pragma unroll
    for (int i = 0; i < 2; i++)
#pragma unroll
        for (int j = 0; j < 4; j++)
#pragma unroll
            for (int c = 0; c < 4; c++) acc[i][j][c] = 0.0f;

    const int S = INTER / 32;  // 24
    dn_load(e, mbase, nbase, 0,  sbase,                tid); CP_COMMIT();
    dn_load(e, mbase, nbase, 32, sbase + DN_STAGE,     tid); CP_COMMIT();
    dn_load(e, mbase, nbase, 64, sbase + 2 * DN_STAGE, tid); CP_COMMIT();

#pragma unroll 1
    for (int s = 0; s < S; s++) {
        CP_WAIT2();
        __syncthreads();
        if (s + 3 < S)
            dn_load(e, mbase, nbase, (s + 3) * 32, sbase + ((s + 3) & 3) * DN_STAGE, tid);
        CP_COMMIT();

        uint32_t st = sbase + (s & 3) * DN_STAGE;
#pragma unroll
        for (int ks = 0; ks < 2; ks++) {
            uint32_t a[2][4];
#pragma unroll
            for (int mt = 0; mt < 2; mt++) {
                uint32_t aa = st + (wm + mt * 16 + (lane & 15)) * 80
                            + (ks * 16 + (lane >> 4) * 8) * 2;
                LDSM4(a[mt], aa);
            }
#pragma unroll
            for (int ng = 0; ng < 2; ng++) {
                uint32_t ba = st + 10240 + (ks * 16 + (lane & 15)) * 144
                            + (wn + ng * 16 + (lane >> 4) * 8) * 2;
                uint32_t bh[4];
                LDSM4T(bh, ba);
#pragma unroll
                for (int half = 0; half < 2; half++) {
                    int j = ng * 2 + half;
#pragma unroll
                    for (int mt = 0; mt < 2; mt++)
                        MMA_F16(acc[mt][j], a[mt], &bh[half * 2]);
                }
            }
        }
    }

    // epilogue: atomic scatter into out
#pragma unroll
    for (int mt = 0; mt < 2; mt++) {
#pragma unroll
        for (int rh = 0; rh < 2; rh++) {
            int m = wm + mt * 16 + (lane >> 2) + rh * 8;
            int tok = stok[m];
            if (tok < 0) continue;
            float* op = &out[(size_t)tok * HID + nbase];
#pragma unroll
            for (int j = 0; j < 4; j++) {
                int col = wn + (j >> 1) * 16 + (j & 1) * 8 + (lane & 3) * 2;
                atomicAdd(op + col,     acc[mt][j][rh * 2 + 0]);
                atomicAdd(op + col + 1, acc[mt][j][rh * 2 + 1]);
            }
        }
    }
}

// ---------------- launch ----------------
extern "C" void kernel_launch(void* const* d_in, const int* in_sizes, int n_in,
                              void* d_out, int out_size)
{
    const float* x    = (const float*)d_in[0];
    const float* rw   = (const float*)d_in[1];
    const float* gup  = (const float*)d_in[2];
    const float* dw   = (const float*)d_in[3];
    float* out = (float*)d_out;

    static bool attr_set = false;
    if (!attr_set) {
        cudaFuncSetAttribute(gateup_mma, cudaFuncAttributeMaxDynamicSharedMemorySize, GU_SMEM);
        cudaFuncSetAttribute(down_mma,   cudaFuncAttributeMaxDynamicSharedMemorySize, DN_SMEM);
        attr_set = true;
    }

    int n_out = T_TOK * HID;
    zero_kernel<<<(n_out + 511) / 512, 512>>>(out, n_out);
    router_kernel<<<T_TOK, 128>>>(x, rw);

    // conversions (fp32 -> fp16)
    {
        __half *xh, *gh, *dh;
        cudaGetSymbolAddress((void**)&xh, g_xh);
        cudaGetSymbolAddress((void**)&gh, g_gh);
        cudaGetSymbolAddress((void**)&dh, g_dh);

        int n4x = T_TOK * HID / 4;
        convh_kernel<<<(n4x + 255) / 256, 256>>>(
            (const float4*)x, (uint2*)xh, n4x);
        int n4g = NEXP * HID * INTER2 / 4;
        convh_kernel<<<(n4g + 255) / 256, 256>>>(
            (const float4*)gup, (uint2*)gh, n4g);
        int n4d = NEXP * INTER * HID / 4;
        convh_kernel<<<(n4d + 255) / 256, 256>>>(
            (const float4*)dw, (uint2*)dh, n4d);
    }

    dim3 gridG(T_TOK / 128, INTER / 64, NEXP);   // (m=8, n=12, e=16)
    gateup_mma<<<gridG, 256, GU_SMEM>>>(0);

    dim3 gridD(T_TOK / 128, HID / 64, NEXP);     // (m=8, n=32, e=16)
    down_mma<<<gridD, 256, DN_SMEM>>>(out);
}

// round 10
// speedup vs baseline: 2.2385x; 1.0025x over previous
#include <cuda_runtime.h>
#include <cuda_fp16.h>
#include <cstdint>

// Problem constants (Qwen3MoeSparseMoeBlock_2413771621126)
#define T_TOK   1024
#define HID     2048
#define NEXP    16
#define TOPK    4
#define INTER   768
#define INTER2  1536

// ---------------- device scratch (static; allocation-free) ----------------
__device__ int   g_cnt[NEXP];
__device__ int   g_tok[NEXP * T_TOK];
__device__ float g_wt [NEXP * T_TOK];

__device__ __align__(128) __half g_xh[(size_t)T_TOK * HID];
__device__ __align__(128) __half g_gh[(size_t)NEXP * HID * INTER2];
__device__ __align__(128) __half g_dh[(size_t)NEXP * INTER * HID];
__device__ __align__(128) __half g_hf[(size_t)NEXP * T_TOK * INTER];

// ---------------- helpers ----------------
__device__ __forceinline__ uint32_t smem_u32(const void* p) {
    uint32_t a;
    asm("{ .reg .u64 t; cvta.to.shared.u64 t, %1; cvt.u32.u64 %0, t; }" : "=r"(a) : "l"(p));
    return a;
}

// fp16 convert of float4 -> 4 fp16 (uint2)
__device__ __forceinline__ uint2 conv4h(float4 f) {
    uint2 r;
    r.x = ((uint32_t)__half_as_ushort(__float2half(f.y)) << 16) | __half_as_ushort(__float2half(f.x));
    r.y = ((uint32_t)__half_as_ushort(__float2half(f.w)) << 16) | __half_as_ushort(__float2half(f.z));
    return r;
}

#define MMA_F16(d, a, b) \
    asm volatile("mma.sync.aligned.m16n8k16.row.col.f32.f16.f16.f32 " \
        "{%0,%1,%2,%3}, {%4,%5,%6,%7}, {%8,%9}, {%0,%1,%2,%3};" \
        : "+f"((d)[0]), "+f"((d)[1]), "+f"((d)[2]), "+f"((d)[3]) \
        : "r"((a)[0]), "r"((a)[1]), "r"((a)[2]), "r"((a)[3]), \
          "r"((b)[0]), "r"((b)[1]))

#define LDSM4(r, a) \
    asm volatile("ldmatrix.sync.aligned.m8n8.x4.shared.b16 {%0,%1,%2,%3}, [%4];" \
        : "=r"((r)[0]), "=r"((r)[1]), "=r"((r)[2]), "=r"((r)[3]) : "r"(a))
#define LDSM4T(r, a) \
    asm volatile("ldmatrix.sync.aligned.m8n8.x4.trans.shared.b16 {%0,%1,%2,%3}, [%4];" \
        : "=r"((r)[0]), "=r"((r)[1]), "=r"((r)[2]), "=r"((r)[3]) : "r"(a))

#define CP16(dst, src) \
    asm volatile("cp.async.cg.shared.global [%0], [%1], 16;" \
        :: "r"(dst), "l"(__cvta_generic_to_global(src)))
#define CP_COMMIT() asm volatile("cp.async.commit_group;" ::: "memory")
#define CP_WAIT2()  asm volatile("cp.async.wait_group 2;" ::: "memory")

// ---------------- phase 0 ----------------
__global__ void zero_kernel(float* __restrict__ out, int n) {
    int i = blockIdx.x * blockDim.x + threadIdx.x;
    if (i < n) out[i] = 0.0f;
    if (blockIdx.x == 0 && threadIdx.x < NEXP) g_cnt[threadIdx.x] = 0;
}

// ---------------- fp32 -> fp16 convert ----------------
__global__ void __launch_bounds__(256) convh_kernel(
    const float4* __restrict__ src, uint2* __restrict__ dst, int n4)
{
    int i = blockIdx.x * blockDim.x + threadIdx.x;
    if (i < n4) dst[i] = conv4h(src[i]);
}

// ---------------- phase 1: router ----------------
__global__ void __launch_bounds__(128) router_kernel(
    const float* __restrict__ x, const float* __restrict__ rw)
{
    int t = blockIdx.x, tid = threadIdx.x;
    float acc[NEXP];
#pragma unroll
    for (int e = 0; e < NEXP; e++) acc[e] = 0.0f;
    const float* xr = x + (size_t)t * HID;
    for (int k = tid; k < HID; k += 128) {
        float xv = xr[k];
#pragma unroll
        for (int e = 0; e < NEXP; e++) acc[e] += xv * rw[e * HID + k];
    }
#pragma unroll
    for (int e = 0; e < NEXP; e++) {
#pragma unroll
        for (int off = 16; off > 0; off >>= 1)
            acc[e] += __shfl_down_sync(0xFFFFFFFFu, acc[e], off);
    }
    __shared__ float spart[4][NEXP];
    int warp = tid >> 5, lane = tid & 31;
    if (lane == 0) {
#pragma unroll
        for (int e = 0; e < NEXP; e++) spart[warp][e] = acc[e];
    }
    __syncthreads();
    if (tid == 0) {
        float logit[NEXP];
#pragma unroll
        for (int e = 0; e < NEXP; e++)
            logit[e] = spart[0][e] + spart[1][e] + spart[2][e] + spart[3][e];
        int idx[TOPK]; float val[TOPK]; bool used[NEXP];
#pragma unroll
        for (int e = 0; e < NEXP; e++) used[e] = false;
#pragma unroll
        for (int k = 0; k < TOPK; k++) {
            float best = -1e30f; int bi = 0;
            for (int e = 0; e < NEXP; e++)
                if (!used[e] && logit[e] > best) { best = logit[e]; bi = e; }
            used[bi] = true; idx[k] = bi; val[k] = best;
        }
        float mx = val[0], s = 0.0f, ev[TOPK];
#pragma unroll
        for (int k = 0; k < TOPK; k++) { ev[k] = expf(val[k] - mx); s += ev[k]; }
        float inv = 1.0f / s;
#pragma unroll
        for (int k = 0; k < TOPK; k++) {
            int e = idx[k];
            int pos = atomicAdd(&g_cnt[e], 1);
            g_tok[e * T_TOK + pos] = t;
            g_wt [e * T_TOK + pos] = ev[k] * inv;
        }
    }
}

// ============================================================
// smem (per stage, bytes), 4-stage cp.async ring:
//  A: 128 x 32 fp16, pitch 80B  -> 10240 @ 0
//  gate_up B: 32k x 128n fp16, pitch 272B -> 8704 @ 10240 ; stage 18944
//  down    B: 32k x  64n fp16, pitch 144B -> 4608 @ 10240 ; stage 14848
// ============================================================
#define GU_STAGE 18944
#define GU_META  (4 * GU_STAGE)
#define GU_SMEM  (GU_META + 1024)
#define DN_STAGE 14848
#define DN_META  (4 * DN_STAGE)
#define DN_SMEM  (DN_META + 1024)

// ---------------- phase 2: gate_up GEMM ----------------
__device__ __forceinline__ void gu_load(
    int e, int nbase, int k0, uint32_t sb, const int* stok, int tid)
{
#pragma unroll
    for (int i = 0; i < 2; i++) {
        int c = tid + i * 256;
        int row = c >> 2, seg = c & 3;
        int tok = stok[row];
        CP16(sb + row * 80 + seg * 16, g_xh + (size_t)tok * HID + k0 + seg * 8);
    }
#pragma unroll
    for (int i = 0; i < 2; i++) {
        int c = tid + i * 256;
        int k = c >> 4, seg = c & 15;
        int n = seg * 8;
        int col = (n < 64) ? (nbase + n) : (INTER + nbase + (n - 64));
        CP16(sb + 10240 + k * 272 + seg * 16,
             g_gh + ((size_t)e * HID + k0 + k) * INTER2 + col);
    }
}

__global__ void __launch_bounds__(256, 2) gateup_mma(int dummy)
{
    extern __shared__ char smem[];
    int e = blockIdx.z;
    int cnt = g_cnt[e];
    int mbase = blockIdx.x * 128;
    if (mbase >= cnt) return;
    int nbase = blockIdx.y * 64;

    int tid = threadIdx.x;
    int lane = tid & 31, wid = tid >> 5;
    int wm = (wid & 3) * 32;
    int wn = (wid >> 2) * 32;

    uint32_t sbase = smem_u32(smem);
    int*   stok = (int*)  (smem + GU_META);
    float* swt  = (float*)(smem + GU_META + 512);
    if (tid < 128) {
        int gm = mbase + tid;
        stok[tid] = (gm < cnt) ? g_tok[e * T_TOK + gm] : 0;
        swt[tid]  = (gm < cnt) ? g_wt [e * T_TOK + gm] : 0.0f;
    }
    __syncthreads();

    float accG[2][4][4], accU[2][4][4];
#pragma unroll
    for (int i = 0; i < 2; i++)
#pragma unroll
        for (int j = 0; j < 4; j++)
#pragma unroll
            for (int c = 0; c < 4; c++) { accG[i][j][c] = 0.0f; accU[i][j][c] = 0.0f; }

    const int S = HID / 32;   // 64
    gu_load(e, nbase, 0,  sbase,                stok, tid); CP_COMMIT();
    gu_load(e, nbase, 32, sbase + GU_STAGE,     stok, tid); CP_COMMIT();
    gu_load(e, nbase, 64, sbase + 2 * GU_STAGE, stok, tid); CP_COMMIT();

#pragma unroll 1
    for (int s = 0; s < S; s++) {
        CP_WAIT2();
        __syncthreads();
        if (s + 3 < S)
            gu_load(e, nbase, (s + 3) * 32, sbase + ((s + 3) & 3) * GU_STAGE, stok, tid);
        CP_COMMIT();

        uint32_t st = sbase + (s & 3) * GU_STAGE;
#pragma unroll
        for (int ks = 0; ks < 2; ks++) {
            uint32_t a[2][4];
#pragma unroll
            for (int mt = 0; mt < 2; mt++) {
                uint32_t aa = st + (wm + mt * 16 + (lane & 15)) * 80
                            + (ks * 16 + (lane >> 4) * 8) * 2;
                LDSM4(a[mt], aa);
            }
#pragma unroll
            for (int ng = 0; ng < 2; ng++) {
                uint32_t ba = st + 10240 + (ks * 16 + (lane & 15)) * 272
                            + (wn + ng * 16 + (lane >> 4) * 8) * 2;
                uint32_t bg[4], bu[4];
                LDSM4T(bg, ba);
                LDSM4T(bu, ba + 128);           // up cols at +64 fp16
#pragma unroll
                for (int half = 0; half < 2; half++) {
                    int j = ng * 2 + half;
#pragma unroll
                    for (int mt = 0; mt < 2; mt++) {
                        MMA_F16(accG[mt][j], a[mt], &bg[half * 2]);
                        MMA_F16(accU[mt][j], a[mt], &bu[half * 2]);
                    }
                }
            }
        }
    }

    // epilogue: h = silu(gate) * up * wt -> fp16 global
#pragma unroll
    for (int mt = 0; mt < 2; mt++) {
#pragma unroll
        for (int j = 0; j < 4; j++) {
            int col = wn + (j >> 1) * 16 + (j & 1) * 8 + (lane & 3) * 2;
#pragma unroll
            for (int rh = 0; rh < 2; rh++) {
                int m = wm + mt * 16 + (lane >> 2) + rh * 8;
                int gm = mbase + m;
                if (gm >= cnt) continue;
                float w = swt[m];
                float g0 = accG[mt][j][rh * 2 + 0], u0 = accU[mt][j][rh * 2 + 0];
                float g1 = accG[mt][j][rh * 2 + 1], u1 = accU[mt][j][rh * 2 + 1];
                float h0 = (g0 / (1.0f + expf(-g0))) * u0 * w;
                float h1 = (g1 / (1.0f + expf(-g1))) * u1 * w;
                uint32_t pk = ((uint32_t)__half_as_ushort(__float2half(h1)) << 16)
                            |  (uint32_t)__half_as_ushort(__float2half(h0));
                size_t off = ((size_t)e * T_TOK + gm) * INTER + nbase + col;
                *reinterpret_cast<uint32_t*>(g_hf + off) = pk;
            }
        }
    }
}

// ---------------- phase 3: down GEMM + atomic scatter ----------------
__device__ __forceinline__ void dn_load(
    int e, int mbase, int nbase, int k0, uint32_t sb, int tid)
{
#pragma unroll
    for (int i = 0; i < 2; i++) {
        int c = tid + i * 256;
        int row = c >> 2, seg = c & 3;
        CP16(sb + row * 80 + seg * 16,
             g_hf + ((size_t)e * T_TOK + mbase + row) * INTER + k0 + seg * 8);
    }
    {
        int k = tid >> 3, seg = tid & 7;
        CP16(sb + 10240 + k * 144 + seg * 16,
             g_dh + ((size_t)e * INTER + k0 + k) * HID + nbase + seg * 8);
    }
}

__global__ void __launch_bounds__(256, 2) down_mma(float* __restrict__ out)
{
    extern __shared__ char smem[];
    int e = blockIdx.z;
    int cnt = g_cnt[e];
    int mbase = blockIdx.x * 128;
    if (mbase >= cnt) return;
    int nbase = blockIdx.y * 64;

    int tid = threadIdx.x;
    int lane = tid & 31, wid = tid >> 5;
    int wm = (wid & 3) * 32;
    int wn = (wid >> 2) * 32;

    uint32_t sbase = smem_u32(smem);
    int* stok = (int*)(smem + DN_META);
    if (tid < 128) {
        int gm = mbase + tid;
        stok[tid] = (gm < cnt) ? g_tok[e * T_TOK + gm] : -1;
    }
    __syncthreads();

    float acc[2][4][4];
#pragma unroll
    for (int i = 0; i < 2; i++)
#pragma unroll
        for (int j = 0; j < 4; j++)
#pragma unroll
            for (int c = 0; c < 4; c++) acc[i][j][c] = 0.0f;

    const int S = INTER / 32;  // 24
    dn_load(e, mbase, nbase, 0,  sbase,                tid); CP_COMMIT();
    dn_load(e, mbase, nbase, 32, sbase + DN_STAGE,     tid); CP_COMMIT();
    dn_load(e, mbase, nbase, 64, sbase + 2 * DN_STAGE, tid); CP_COMMIT();

#pragma unroll 1
    for (int s = 0; s < S; s++) {
        CP_WAIT2();
        __syncthreads();
        if (s + 3 < S)
            dn_load(e, mbase, nbase, (s + 3) * 32, sbase + ((s + 3) & 3) * DN_STAGE, tid);
        CP_COMMIT();

        uint32_t st = sbase + (s & 3) * DN_STAGE;
#pragma unroll
        for (int ks = 0; ks < 2; ks++) {
            uint32_t a[2][4];
#pragma unroll
            for (int mt = 0; mt < 2; mt++) {
                uint32_t aa = st + (wm + mt * 16 + (lane & 15)) * 80
                            + (ks * 16 + (lane >> 4) * 8) * 2;
                LDSM4(a[mt], aa);
            }
#pragma unroll
            for (int ng = 0; ng < 2; ng++) {
                uint32_t ba = st + 10240 + (ks * 16 + (lane & 15)) * 144
                            + (wn + ng * 16 + (lane >> 4) * 8) * 2;
                uint32_t bh[4];
                LDSM4T(bh, ba);
#pragma unroll
                for (int half = 0; half < 2; half++) {
                    int j = ng * 2 + half;
#pragma unroll
                    for (int mt = 0; mt < 2; mt++)
                        MMA_F16(acc[mt][j], a[mt], &bh[half * 2]);
                }
            }
        }
    }

    // epilogue: atomic scatter into out
#pragma unroll
    for (int mt = 0; mt < 2; mt++) {
#pragma unroll
        for (int rh = 0; rh < 2; rh++) {
            int m = wm + mt * 16 + (lane >> 2) + rh * 8;
            int tok = stok[m];
            if (tok < 0) continue;
            float* op = &out[(size_t)tok * HID + nbase];
#pragma unroll
            for (int j = 0; j < 4; j++) {
                int col = wn + (j >> 1) * 16 + (j & 1) * 8 + (lane & 3) * 2;
                atomicAdd(op + col,     acc[mt][j][rh * 2 + 0]);
                atomicAdd(op + col + 1, acc[mt][j][rh * 2 + 1]);
            }
        }
    }
}

// ---------------- launch (fork-join: weight converts on side stream) -------
extern "C" void kernel_launch(void* const* d_in, const int* in_sizes, int n_in,
                              void* d_out, int out_size)
{
    const float* x    = (const float*)d_in[0];
    const float* rw   = (const float*)d_in[1];
    const float* gup  = (const float*)d_in[2];
    const float* dw   = (const float*)d_in[3];
    float* out = (float*)d_out;

    static cudaStream_t s2 = nullptr;
    static cudaEvent_t  ev_fork = nullptr, ev_gup = nullptr, ev_dw = nullptr;
    static bool init_done = false;
    if (!init_done) {
        cudaFuncSetAttribute(gateup_mma, cudaFuncAttributeMaxDynamicSharedMemorySize, GU_SMEM);
        cudaFuncSetAttribute(down_mma,   cudaFuncAttributeMaxDynamicSharedMemorySize, DN_SMEM);
        cudaStreamCreateWithFlags(&s2, cudaStreamNonBlocking);
        cudaEventCreateWithFlags(&ev_fork, cudaEventDisableTiming);
        cudaEventCreateWithFlags(&ev_gup,  cudaEventDisableTiming);
        cudaEventCreateWithFlags(&ev_dw,   cudaEventDisableTiming);
        init_done = true;
    }

    __half *xh, *gh, *dh;
    cudaGetSymbolAddress((void**)&xh, g_xh);
    cudaGetSymbolAddress((void**)&gh, g_gh);
    cudaGetSymbolAddress((void**)&dh, g_dh);

    cudaStream_t s1 = 0;  // capture (legacy default) stream

    // fork side stream
    cudaEventRecord(ev_fork, s1);
    cudaStreamWaitEvent(s2, ev_fork, 0);

    // side stream: weight conversions
    int n4g = NEXP * HID * INTER2 / 4;
    convh_kernel<<<(n4g + 255) / 256, 256, 0, s2>>>(
        (const float4*)gup, (uint2*)gh, n4g);
    cudaEventRecord(ev_gup, s2);
    int n4d = NEXP * INTER * HID / 4;
    convh_kernel<<<(n4d + 255) / 256, 256, 0, s2>>>(
        (const float4*)dw, (uint2*)dh, n4d);
    cudaEventRecord(ev_dw, s2);

    // main stream: zero + router + x convert (concurrent with gup convert)
    int n_out = T_TOK * HID;
    zero_kernel<<<(n_out + 511) / 512, 512, 0, s1>>>(out, n_out);
    router_kernel<<<T_TOK, 128, 0, s1>>>(x, rw);
    int n4x = T_TOK * HID / 4;
    convh_kernel<<<(n4x + 255) / 256, 256, 0, s1>>>(
        (const float4*)x, (uint2*)xh, n4x);

    // gateup needs gup fp16
    cudaStreamWaitEvent(s1, ev_gup, 0);
    dim3 gridG(T_TOK / 128, INTER / 64, NEXP);   // (m=8, n=12, e=16)
    gateup_mma<<<gridG, 256, GU_SMEM, s1>>>(0);

    // down needs dw fp16 (converted concurrently with gateup)
    cudaStreamWaitEvent(s1, ev_dw, 0);
    dim3 gridD(T_TOK / 128, HID / 64, NEXP);     // (m=8, n=32, e=16)
    down_mma<<<gridD, 256, DN_SMEM, s1>>>(out);
}

// round 11
// speedup vs baseline: 2.3155x; 1.0344x over previous
#include <cuda_runtime.h>
#include <cuda_fp16.h>
#include <cstdint>

// Problem constants (Qwen3MoeSparseMoeBlock_2413771621126)
#define T_TOK   1024
#define HID     2048
#define NEXP    16
#define TOPK    4
#define INTER   768
#define INTER2  1536

// ---------------- device scratch (static; allocation-free) ----------------
__device__ int   g_cnt[NEXP];
__device__ int   g_tok[NEXP * T_TOK];
__device__ float g_wt [NEXP * T_TOK];

__device__ __align__(128) __half g_xh[(size_t)T_TOK * HID];
__device__ __align__(128) __half g_gh[(size_t)NEXP * HID * INTER2];
__device__ __align__(128) __half g_dh[(size_t)NEXP * INTER * HID];
__device__ __align__(128) __half g_hf[(size_t)NEXP * T_TOK * INTER];

// ---------------- helpers ----------------
__device__ __forceinline__ uint32_t smem_u32(const void* p) {
    uint32_t a;
    asm("{ .reg .u64 t; cvta.to.shared.u64 t, %1; cvt.u32.u64 %0, t; }" : "=r"(a) : "l"(p));
    return a;
}

// fp16 convert of float4 -> 4 fp16 (uint2)
__device__ __forceinline__ uint2 conv4h(float4 f) {
    uint2 r;
    r.x = ((uint32_t)__half_as_ushort(__float2half(f.y)) << 16) | __half_as_ushort(__float2half(f.x));
    r.y = ((uint32_t)__half_as_ushort(__float2half(f.w)) << 16) | __half_as_ushort(__float2half(f.z));
    return r;
}

#define MMA_F16(d, a, b) \
    asm volatile("mma.sync.aligned.m16n8k16.row.col.f32.f16.f16.f32 " \
        "{%0,%1,%2,%3}, {%4,%5,%6,%7}, {%8,%9}, {%0,%1,%2,%3};" \
        : "+f"((d)[0]), "+f"((d)[1]), "+f"((d)[2]), "+f"((d)[3]) \
        : "r"((a)[0]), "r"((a)[1]), "r"((a)[2]), "r"((a)[3]), \
          "r"((b)[0]), "r"((b)[1]))

#define LDSM4(r, a) \
    asm volatile("ldmatrix.sync.aligned.m8n8.x4.shared.b16 {%0,%1,%2,%3}, [%4];" \
        : "=r"((r)[0]), "=r"((r)[1]), "=r"((r)[2]), "=r"((r)[3]) : "r"(a))
#define LDSM4T(r, a) \
    asm volatile("ldmatrix.sync.aligned.m8n8.x4.trans.shared.b16 {%0,%1,%2,%3}, [%4];" \
        : "=r"((r)[0]), "=r"((r)[1]), "=r"((r)[2]), "=r"((r)[3]) : "r"(a))

#define CP16(dst, src) \
    asm volatile("cp.async.cg.shared.global [%0], [%1], 16;" \
        :: "r"(dst), "l"(__cvta_generic_to_global(src)))
#define CP_COMMIT() asm volatile("cp.async.commit_group;" ::: "memory")
#define CP_WAIT2()  asm volatile("cp.async.wait_group 2;" ::: "memory")

// ---------------- phase 0 ----------------
__global__ void zero_kernel(float* __restrict__ out, int n) {
    int i = blockIdx.x * blockDim.x + threadIdx.x;
    if (i < n) out[i] = 0.0f;
    if (blockIdx.x == 0 && threadIdx.x < NEXP) g_cnt[threadIdx.x] = 0;
}

// ---------------- fp32 -> fp16 convert (weights) ----------------
__global__ void __launch_bounds__(256) convh_kernel(
    const float4* __restrict__ src, uint2* __restrict__ dst, int n4)
{
    int i = blockIdx.x * blockDim.x + threadIdx.x;
    if (i < n4) dst[i] = conv4h(src[i]);
}

// ---------------- phase 1: router (+ fused x fp16 convert) ----------------
// 128 blocks x 256 threads; 8 tokens/block, one warp per token.
// router_weight staged through smem in 512-k chunks, shared by all warps.
__global__ void __launch_bounds__(256) router_kernel(
    const float* __restrict__ x, const float* __restrict__ rw,
    __half* __restrict__ xh)
{
    __shared__ float4 rw_s[NEXP][130];   // 512 k floats per expert (pitch 130 float4)

    int tid  = threadIdx.x;
    int lane = tid & 31;
    int w    = tid >> 5;                 // warp = local token
    int t    = blockIdx.x * 8 + w;

    float acc[NEXP];
#pragma unroll
    for (int e = 0; e < NEXP; e++) acc[e] = 0.0f;

#pragma unroll 1
    for (int c = 0; c < HID / 512; c++) {   // 4 chunks
        __syncthreads();
        // stage rw chunk: 16 experts x 128 float4
        for (int i = tid; i < NEXP * 128; i += 256) {
            int e = i >> 7, k4 = i & 127;
            rw_s[e][k4] = reinterpret_cast<const float4*>(rw + e * HID + c * 512)[k4];
        }
        __syncthreads();

        const float4* xp = reinterpret_cast<const float4*>(x + (size_t)t * HID + c * 512);
#pragma unroll
        for (int i = 0; i < 4; i++) {
            int k4 = lane + i * 32;
            float4 xv = xp[k4];
            // fused x fp16 convert (each element covered exactly once)
            *reinterpret_cast<uint2*>(xh + (size_t)t * HID + c * 512 + k4 * 4) = conv4h(xv);
#pragma unroll
            for (int e = 0; e < NEXP; e++) {
                float4 rv = rw_s[e][k4];
                acc[e] += xv.x * rv.x + xv.y * rv.y + xv.z * rv.z + xv.w * rv.w;
            }
        }
    }

    // warp reduction of 16 logits
#pragma unroll
    for (int e = 0; e < NEXP; e++) {
#pragma unroll
        for (int off = 16; off > 0; off >>= 1)
            acc[e] += __shfl_down_sync(0xFFFFFFFFu, acc[e], off);
    }

    if (lane == 0) {
        int idx[TOPK]; float val[TOPK]; bool used[NEXP];
#pragma unroll
        for (int e = 0; e < NEXP; e++) used[e] = false;
#pragma unroll
        for (int k = 0; k < TOPK; k++) {
            float best = -1e30f; int bi = 0;
            for (int e = 0; e < NEXP; e++)
                if (!used[e] && acc[e] > best) { best = acc[e]; bi = e; }
            used[bi] = true; idx[k] = bi; val[k] = best;
        }
        float mx = val[0], s = 0.0f, ev[TOPK];
#pragma unroll
        for (int k = 0; k < TOPK; k++) { ev[k] = expf(val[k] - mx); s += ev[k]; }
        float inv = 1.0f / s;
#pragma unroll
        for (int k = 0; k < TOPK; k++) {
            int e = idx[k];
            int pos = atomicAdd(&g_cnt[e], 1);
            g_tok[e * T_TOK + pos] = t;
            g_wt [e * T_TOK + pos] = ev[k] * inv;
        }
    }
}

// ============================================================
// smem (per stage, bytes), 4-stage cp.async ring:
//  A: 128 x 32 fp16, pitch 80B  -> 10240 @ 0
//  gate_up B: 32k x 128n fp16, pitch 272B -> 8704 @ 10240 ; stage 18944
//  down    B: 32k x  64n fp16, pitch 144B -> 4608 @ 10240 ; stage 14848
// ============================================================
#define GU_STAGE 18944
#define GU_META  (4 * GU_STAGE)
#define GU_SMEM  (GU_META + 1024)
#define DN_STAGE 14848
#define DN_META  (4 * DN_STAGE)
#define DN_SMEM  (DN_META + 1024)

// ---------------- phase 2: gate_up GEMM ----------------
__device__ __forceinline__ void gu_load(
    int e, int nbase, int k0, uint32_t sb, const int* stok, int tid)
{
#pragma unroll
    for (int i = 0; i < 2; i++) {
        int c = tid + i * 256;
        int row = c >> 2, seg = c & 3;
        int tok = stok[row];
        CP16(sb + row * 80 + seg * 16, g_xh + (size_t)tok * HID + k0 + seg * 8);
    }
#pragma unroll
    for (int i = 0; i < 2; i++) {
        int c = tid + i * 256;
        int k = c >> 4, seg = c & 15;
        int n = seg * 8;
        int col = (n < 64) ? (nbase + n) : (INTER + nbase + (n - 64));
        CP16(sb + 10240 + k * 272 + seg * 16,
             g_gh + ((size_t)e * HID + k0 + k) * INTER2 + col);
    }
}

__global__ void __launch_bounds__(256, 2) gateup_mma(int dummy)
{
    extern __shared__ char smem[];
    int e = blockIdx.z;
    int cnt = g_cnt[e];
    int mbase = blockIdx.x * 128;
    if (mbase >= cnt) return;
    int nbase = blockIdx.y * 64;

    int tid = threadIdx.x;
    int lane = tid & 31, wid = tid >> 5;
    int wm = (wid & 3) * 32;
    int wn = (wid >> 2) * 32;

    uint32_t sbase = smem_u32(smem);
    int*   stok = (int*)  (smem + GU_META);
    float* swt  = (float*)(smem + GU_META + 512);
    if (tid < 128) {
        int gm = mbase + tid;
        stok[tid] = (gm < cnt) ? g_tok[e * T_TOK + gm] : 0;
        swt[tid]  = (gm < cnt) ? g_wt [e * T_TOK + gm] : 0.0f;
    }
    __syncthreads();

    float accG[2][4][4], accU[2][4][4];
#pragma unroll
    for (int i = 0; i < 2; i++)
#pragma unroll
        for (int j = 0; j < 4; j++)
#pragma unroll
            for (int c = 0; c < 4; c++) { accG[i][j][c] = 0.0f; accU[i][j][c] = 0.0f; }

    const int S = HID / 32;   // 64
    gu_load(e, nbase, 0,  sbase,                stok, tid); CP_COMMIT();
    gu_load(e, nbase, 32, sbase + GU_STAGE,     stok, tid); CP_COMMIT();
    gu_load(e, nbase, 64, sbase + 2 * GU_STAGE, stok, tid); CP_COMMIT();

#pragma unroll 1
    for (int s = 0; s < S; s++) {
        CP_WAIT2();
        __syncthreads();
        if (s + 3 < S)
            gu_load(e, nbase, (s + 3) * 32, sbase + ((s + 3) & 3) * GU_STAGE, stok, tid);
        CP_COMMIT();

        uint32_t st = sbase + (s & 3) * GU_STAGE;
#pragma unroll
        for (int ks = 0; ks < 2; ks++) {
            uint32_t a[2][4];
#pragma unroll
            for (int mt = 0; mt < 2; mt++) {
                uint32_t aa = st + (wm + mt * 16 + (lane & 15)) * 80
                            + (ks * 16 + (lane >> 4) * 8) * 2;
                LDSM4(a[mt], aa);
            }
#pragma unroll
            for (int ng = 0; ng < 2; ng++) {
                uint32_t ba = st + 10240 + (ks * 16 + (lane & 15)) * 272
                            + (wn + ng * 16 + (lane >> 4) * 8) * 2;
                uint32_t bg[4], bu[4];
                LDSM4T(bg, ba);
                LDSM4T(bu, ba + 128);           // up cols at +64 fp16
#pragma unroll
                for (int half = 0; half < 2; half++) {
                    int j = ng * 2 + half;
#pragma unroll
                    for (int mt = 0; mt < 2; mt++) {
                        MMA_F16(accG[mt][j], a[mt], &bg[half * 2]);
                        MMA_F16(accU[mt][j], a[mt], &bu[half * 2]);
                    }
                }
            }
        }
    }

    // epilogue: h = silu(gate) * up * wt -> fp16 global
#pragma unroll
    for (int mt = 0; mt < 2; mt++) {
#pragma unroll
        for (int j = 0; j < 4; j++) {
            int col = wn + (j >> 1) * 16 + (j & 1) * 8 + (lane & 3) * 2;
#pragma unroll
            for (int rh = 0; rh < 2; rh++) {
                int m = wm + mt * 16 + (lane >> 2) + rh * 8;
                int gm = mbase + m;
                if (gm >= cnt) continue;
                float w = swt[m];
                float g0 = accG[mt][j][rh * 2 + 0], u0 = accU[mt][j][rh * 2 + 0];
                float g1 = accG[mt][j][rh * 2 + 1], u1 = accU[mt][j][rh * 2 + 1];
                float h0 = (g0 / (1.0f + expf(-g0))) * u0 * w;
                float h1 = (g1 / (1.0f + expf(-g1))) * u1 * w;
                uint32_t pk = ((uint32_t)__half_as_ushort(__float2half(h1)) << 16)
                            |  (uint32_t)__half_as_ushort(__float2half(h0));
                size_t off = ((size_t)e * T_TOK + gm) * INTER + nbase + col;
                *reinterpret_cast<uint32_t*>(g_hf + off) = pk;
            }
        }
    }
}

// ---------------- phase 3: down GEMM + atomic scatter ----------------
__device__ __forceinline__ void dn_load(
    int e, int mbase, int nbase, int k0, uint32_t sb, int tid)
{
#pragma unroll
    for (int i = 0; i < 2; i++) {
        int c = tid + i * 256;
        int row = c >> 2, seg = c & 3;
        CP16(sb + row * 80 + seg * 16,
             g_hf + ((size_t)e * T_TOK + mbase + row) * INTER + k0 + seg * 8);
    }
    {
        int k = tid >> 3, seg = tid & 7;
        CP16(sb + 10240 + k * 144 + seg * 16,
             g_dh + ((size_t)e * INTER + k0 + k) * HID + nbase + seg * 8);
    }
}

__global__ void __launch_bounds__(256, 2) down_mma(float* __restrict__ out)
{
    extern __shared__ char smem[];
    int e = blockIdx.z;
    int cnt = g_cnt[e];
    int mbase = blockIdx.x * 128;
    if (mbase >= cnt) return;
    int nbase = blockIdx.y * 64;

    int tid = threadIdx.x;
    int lane = tid & 31, wid = tid >> 5;
    int wm = (wid & 3) * 32;
    int wn = (wid >> 2) * 32;

    uint32_t sbase = smem_u32(smem);
    int* stok = (int*)(smem + DN_META);
    if (tid < 128) {
        int gm = mbase + tid;
        stok[tid] = (gm < cnt) ? g_tok[e * T_TOK + gm] : -1;
    }
    __syncthreads();

    float acc[2][4][4];
#pragma unroll
    for (int i = 0; i < 2; i++)
#pragma unroll
        for (int j = 0; j < 4; j++)
#pragma unroll
            for (int c = 0; c < 4; c++) acc[i][j][c] = 0.0f;

    const int S = INTER / 32;  // 24
    dn_load(e, mbase, nbase, 0,  sbase,                tid); CP_COMMIT();
    dn_load(e, mbase, nbase, 32, sbase + DN_STAGE,     tid); CP_COMMIT();
    dn_load(e, mbase, nbase, 64, sbase + 2 * DN_STAGE, tid); CP_COMMIT();

#pragma unroll 1
    for (int s = 0; s < S; s++) {
        CP_WAIT2();
        __syncthreads();
        if (s + 3 < S)
            dn_load(e, mbase, nbase, (s + 3) * 32, sbase + ((s + 3) & 3) * DN_STAGE, tid);
        CP_COMMIT();

        uint32_t st = sbase + (s & 3) * DN_STAGE;
#pragma unroll
        for (int ks = 0; ks < 2; ks++) {
            uint32_t a[2][4];
#pragma unroll
            for (int mt = 0; mt < 2; mt++) {
                uint32_t aa = st + (wm + mt * 16 + (lane & 15)) * 80
                            + (ks * 16 + (lane >> 4) * 8) * 2;
                LDSM4(a[mt], aa);
            }
#pragma unroll
            for (int ng = 0; ng < 2; ng++) {
                uint32_t ba = st + 10240 + (ks * 16 + (lane & 15)) * 144
                            + (wn + ng * 16 + (lane >> 4) * 8) * 2;
                uint32_t bh[4];
                LDSM4T(bh, ba);
#pragma unroll
                for (int half = 0; half < 2; half++) {
                    int j = ng * 2 + half;
#pragma unroll
                    for (int mt = 0; mt < 2; mt++)
                        MMA_F16(acc[mt][j], a[mt], &bh[half * 2]);
                }
            }
        }
    }

    // epilogue: atomic scatter into out
#pragma unroll
    for (int mt = 0; mt < 2; mt++) {
#pragma unroll
        for (int rh = 0; rh < 2; rh++) {
            int m = wm + mt * 16 + (lane >> 2) + rh * 8;
            int tok = stok[m];
            if (tok < 0) continue;
            float* op = &out[(size_t)tok * HID + nbase];
#pragma unroll
            for (int j = 0; j < 4; j++) {
                int col = wn + (j >> 1) * 16 + (j & 1) * 8 + (lane & 3) * 2;
                atomicAdd(op + col,     acc[mt][j][rh * 2 + 0]);
                atomicAdd(op + col + 1, acc[mt][j][rh * 2 + 1]);
            }
        }
    }
}

// ---------------- launch (fork-join: weight converts on side stream) -------
extern "C" void kernel_launch(void* const* d_in, const int* in_sizes, int n_in,
                              void* d_out, int out_size)
{
    const float* x    = (const float*)d_in[0];
    const float* rw   = (const float*)d_in[1];
    const float* gup  = (const float*)d_in[2];
    const float* dw   = (const float*)d_in[3];
    float* out = (float*)d_out;

    static cudaStream_t s2 = nullptr;
    static cudaEvent_t  ev_fork = nullptr, ev_gup = nullptr, ev_dw = nullptr;
    static bool init_done = false;
    if (!init_done) {
        cudaFuncSetAttribute(gateup_mma, cudaFuncAttributeMaxDynamicSharedMemorySize, GU_SMEM);
        cudaFuncSetAttribute(down_mma,   cudaFuncAttributeMaxDynamicSharedMemorySize, DN_SMEM);
        cudaStreamCreateWithFlags(&s2, cudaStreamNonBlocking);
        cudaEventCreateWithFlags(&ev_fork, cudaEventDisableTiming);
        cudaEventCreateWithFlags(&ev_gup,  cudaEventDisableTiming);
        cudaEventCreateWithFlags(&ev_dw,   cudaEventDisableTiming);
        init_done = true;
    }

    __half *xh, *gh, *dh;
    cudaGetSymbolAddress((void**)&xh, g_xh);
    cudaGetSymbolAddress((void**)&gh, g_gh);
    cudaGetSymbolAddress((void**)&dh, g_dh);

    cudaStream_t s1 = 0;  // capture (legacy default) stream

    // fork side stream
    cudaEventRecord(ev_fork, s1);
    cudaStreamWaitEvent(s2, ev_fork, 0);

    // side stream: weight conversions
    int n4g = NEXP * HID * INTER2 / 4;
    convh_kernel<<<(n4g + 255) / 256, 256, 0, s2>>>(
        (const float4*)gup, (uint2*)gh, n4g);
    cudaEventRecord(ev_gup, s2);
    int n4d = NEXP * INTER * HID / 4;
    convh_kernel<<<(n4d + 255) / 256, 256, 0, s2>>>(
        (const float4*)dw, (uint2*)dh, n4d);
    cudaEventRecord(ev_dw, s2);

    // main stream: zero + router (router also produces fp16 x)
    int n_out = T_TOK * HID;
    zero_kernel<<<(n_out + 511) / 512, 512, 0, s1>>>(out, n_out);
    router_kernel<<<T_TOK / 8, 256, 0, s1>>>(x, rw, xh);

    // gateup needs gup fp16
    cudaStreamWaitEvent(s1, ev_gup, 0);
    dim3 gridG(T_TOK / 128, INTER / 64, NEXP);   // (m=8, n=12, e=16)
    gateup_mma<<<gridG, 256, GU_SMEM, s1>>>(0);

    // down needs dw fp16 (converted concurrently with gateup)
    cudaStreamWaitEvent(s1, ev_dw, 0);
    dim3 gridD(T_TOK / 128, HID / 64, NEXP);     // (m=8, n=32, e=16)
    down_mma<<<gridD, 256, DN_SMEM, s1>>>(out);
}